// round 2
// baseline (speedup 1.0000x reference)
#include <cuda_runtime.h>
#include <cstdint>
#include <cstddef>

// ============================================================
// Problem constants (fixed by the dataset)
// ============================================================
#define MAX_E   320000
#define NRBF    16
#define DH      64
#define NW      288      // 9 paths * 32 channels
#define CMUL    32

// scratch for per-edge MLP outputs w (E x 288), fp32
__device__ float g_w[(size_t)MAX_E * NW];

// ============================================================
// Compile-time Clebsch-Gordan (exact port of the reference math)
// All helpers are __host__ __device__ constexpr so they are legal in
// device code without --expt-relaxed-constexpr; they fold at compile time.
// ============================================================
struct CD { double re, im; };
__host__ __device__ constexpr CD cmulc(CD a, CD b){ return CD{a.re*b.re - a.im*b.im, a.re*b.im + a.im*b.re}; }
__host__ __device__ constexpr CD conjc(CD a){ return CD{a.re, -a.im}; }
__host__ __device__ constexpr double cfact(int n){ double r=1.0; for(int i=2;i<=n;++i) r*= (double)i; return r; }
__host__ __device__ constexpr double csqrt(double x){
  if (x <= 0.0) return 0.0;
  double r = x < 1.0 ? 1.0 : x;
  for (int i=0;i<200;++i) r = 0.5*(r + x/r);
  return r;
}
__host__ __device__ constexpr double cgc(int l1,int l2,int l3,int m1,int m2){
  int m3 = m1+m2;
  if (m3 < -l3 || m3 > l3) return 0.0;
  double pref = csqrt((double)(2*l3+1)*cfact(l1+l2-l3)*cfact(l1-l2+l3)*cfact(-l1+l2+l3)/cfact(l1+l2+l3+1));
  pref *= csqrt(cfact(l3+m3)*cfact(l3-m3)*cfact(l1-m1)*cfact(l1+m1)*cfact(l2-m2)*cfact(l2+m2));
  double s = 0.0;
  for (int k=0;k<=l1+l2-l3;++k){
    int a1=l1+l2-l3-k, a2=l1-m1-k, a3=l2+m2-k, a4=l3-l2+m1+k, a5=l3-l1-m2+k;
    if (a1<0||a2<0||a3<0||a4<0||a5<0) continue;
    double d = cfact(k)*cfact(a1)*cfact(a2)*cfact(a3)*cfact(a4)*cfact(a5);
    s += ((k&1)? -1.0 : 1.0)/d;
  }
  return pref*s;
}
struct UMat { CD u[5][5]; };
__host__ __device__ constexpr UMat makeU(int l){
  UMat U{};
  const double s = 1.0/csqrt(2.0);
  U.u[l][l] = CD{1.0, 0.0};
  for (int m=1;m<=l;++m){
    double sg = (m&1)? -1.0 : 1.0;
    U.u[l+m][l+m] = CD{sg*s, 0.0};
    U.u[l+m][l-m] = CD{s, 0.0};
    U.u[l-m][l-m] = CD{0.0, s};
    U.u[l-m][l+m] = CD{0.0, -sg*s};
  }
  return U;
}
struct CG3 { double v[5][5][5]; };
__host__ __device__ constexpr CG3 make_cg(int l1,int l2,int l3){
  UMat U1 = makeU(l1), U2 = makeU(l2), U3 = makeU(l3);
  int n1=2*l1+1, n2=2*l2+1, n3=2*l3+1;
  double tre[5][5][5] = {}, tim[5][5][5] = {};
  double mre=0.0, mim=0.0;
  for (int a=0;a<n1;++a) for (int b=0;b<n2;++b) for (int c=0;c<n3;++c){
    CD acc{0.0,0.0};
    for (int m=0;m<n1;++m) for (int n=0;n<n2;++n){
      int o = (m-l1)+(n-l2)+l3;
      if (o < 0 || o >= n3) continue;
      double cg = cgc(l1,l2,l3, m-l1, n-l2);
      if (cg == 0.0) continue;
      CD t = cmulc(cmulc(U1.u[a][m], U2.u[b][n]), conjc(U3.u[c][o]));
      acc.re += t.re*cg; acc.im += t.im*cg;
    }
    tre[a][b][c]=acc.re; tim[a][b][c]=acc.im;
    double ar = acc.re<0.0?-acc.re:acc.re;
    double ai = acc.im<0.0?-acc.im:acc.im;
    if (ar>mre) mre=ar;
    if (ai>mim) mim=ai;
  }
  CG3 R{};
  for (int a=0;a<n1;++a) for (int b=0;b<n2;++b) for (int c=0;c<n3;++c){
    double vv = (mre >= mim) ? tre[a][b][c] : tim[a][b][c];
    if (vv < 1e-12 && vv > -1e-12) vv = 0.0;
    R.v[a][b][c] = vv;
  }
  return R;
}

// ============================================================
// FFMA2: packed fp32 x2 FMA (sm_100+ PTX only; ptxas never emits it
// from plain C++). Doubles fp32 MAC throughput on the fma pipe.
// ============================================================
union F2U { float2 f; unsigned long long u; };
__device__ __forceinline__ float2 ffma2(float2 a, float2 b, float2 c){
  F2U A, B, C, D;
  A.f = a; B.f = b; C.f = c;
  asm("fma.rn.f32x2 %0, %1, %2, %3;" : "=l"(D.u) : "l"(A.u), "l"(B.u), "l"(C.u));
  return D.f;
}

__device__ __forceinline__ float silu(float x){
  return x / (1.0f + __expf(-x));
}

// ============================================================
// Kernel A: per-edge MLP  w = silu(silu(silu(ef@W0)@W1)@W2)
// One thread per edge; weights staged in shared memory.
// ============================================================
#define SMEM_FLOATS (NRBF*DH + DH*DH + DH*NW)   // 1024 + 4096 + 18432 = 23552

template<int IN, int OUT>
__device__ __forceinline__ void dense_silu(const float* __restrict__ x,
                                           const float* __restrict__ sW,
                                           float* __restrict__ y){
  #pragma unroll 1
  for (int j = 0; j < OUT; j += 8){
    float2 a0 = {0.f,0.f}, a1 = {0.f,0.f}, a2 = {0.f,0.f}, a3 = {0.f,0.f};
    #pragma unroll
    for (int k = 0; k < IN; ++k){
      float2 xx = make_float2(x[k], x[k]);
      float4 w01 = *reinterpret_cast<const float4*>(sW + k*OUT + j);
      float4 w23 = *reinterpret_cast<const float4*>(sW + k*OUT + j + 4);
      a0 = ffma2(xx, make_float2(w01.x, w01.y), a0);
      a1 = ffma2(xx, make_float2(w01.z, w01.w), a1);
      a2 = ffma2(xx, make_float2(w23.x, w23.y), a2);
      a3 = ffma2(xx, make_float2(w23.z, w23.w), a3);
    }
    y[j+0] = silu(a0.x); y[j+1] = silu(a0.y);
    y[j+2] = silu(a1.x); y[j+3] = silu(a1.y);
    y[j+4] = silu(a2.x); y[j+5] = silu(a2.y);
    y[j+6] = silu(a3.x); y[j+7] = silu(a3.y);
  }
}

__global__ __launch_bounds__(256)
void mlp_kernel(const float* __restrict__ ef,
                const float* __restrict__ W0,
                const float* __restrict__ W1,
                const float* __restrict__ W2,
                int E){
  extern __shared__ float s[];
  float* sW0 = s;
  float* sW1 = s + NRBF*DH;
  float* sW2 = s + NRBF*DH + DH*DH;
  for (int i = threadIdx.x; i < NRBF*DH; i += blockDim.x) sW0[i] = W0[i];
  for (int i = threadIdx.x; i < DH*DH;   i += blockDim.x) sW1[i] = W1[i];
  for (int i = threadIdx.x; i < DH*NW;   i += blockDim.x) sW2[i] = W2[i];
  __syncthreads();

  int e = blockIdx.x * blockDim.x + threadIdx.x;
  if (e >= E) return;

  float x[NRBF];
  #pragma unroll
  for (int i = 0; i < NRBF/4; ++i){
    float4 t = reinterpret_cast<const float4*>(ef + (size_t)e*NRBF)[i];
    x[4*i+0]=t.x; x[4*i+1]=t.y; x[4*i+2]=t.z; x[4*i+3]=t.w;
  }
  float h1[DH];
  dense_silu<NRBF, DH>(x, sW0, h1);
  float h2[DH];
  dense_silu<DH, DH>(h1, sW1, h2);

  // layer 3: 64 -> 288, write straight to scratch
  float* wout = g_w + (size_t)e * NW;
  #pragma unroll 1
  for (int j = 0; j < NW; j += 8){
    float2 a0 = {0.f,0.f}, a1 = {0.f,0.f}, a2 = {0.f,0.f}, a3 = {0.f,0.f};
    #pragma unroll
    for (int k = 0; k < DH; ++k){
      float2 xx = make_float2(h2[k], h2[k]);
      float4 w01 = *reinterpret_cast<const float4*>(sW2 + k*NW + j);
      float4 w23 = *reinterpret_cast<const float4*>(sW2 + k*NW + j + 4);
      a0 = ffma2(xx, make_float2(w01.x, w01.y), a0);
      a1 = ffma2(xx, make_float2(w01.z, w01.w), a1);
      a2 = ffma2(xx, make_float2(w23.x, w23.y), a2);
      a3 = ffma2(xx, make_float2(w23.z, w23.w), a3);
    }
    float4 o0 = make_float4(silu(a0.x), silu(a0.y), silu(a1.x), silu(a1.y));
    float4 o1 = make_float4(silu(a2.x), silu(a2.y), silu(a3.x), silu(a3.y));
    *reinterpret_cast<float4*>(wout + j)     = o0;
    *reinterpret_cast<float4*>(wout + j + 4) = o1;
  }
}

// ============================================================
// Kernel B: tensor product + scatter-add.
// One warp per edge, one lane per channel u (CMUL == 32).
// CG nonzeros fold to compile-time immediates.
// ============================================================
template<int L1, int L2, int L3>
__device__ __forceinline__ void do_path(float wp, const float* x, const float* Y, float* o){
  constexpr CG3 cg = make_cg(L1, L2, L3);
  #pragma unroll
  for (int a = 0; a < 2*L1+1; ++a){
    float wx = wp * x[a];
    #pragma unroll
    for (int b = 0; b < 2*L2+1; ++b){
      #pragma unroll
      for (int c = 0; c < 2*L3+1; ++c){
        const float v = (float)cg.v[a][b][c];
        if (v != 0.0f){
          o[c] += wx * (v * Y[b]);
        }
      }
    }
  }
}

__global__ __launch_bounds__(256)
void tp_kernel(const float* __restrict__ nf,
               const float* __restrict__ evec,
               const int*   __restrict__ eidx,
               float* __restrict__ out,
               int E){
  int warp = (blockIdx.x * blockDim.x + threadIdx.x) >> 5;
  int lane = threadIdx.x & 31;
  if (warp >= E) return;
  int e = warp;

  int src = eidx[2*e+0];
  int dst = eidx[2*e+1];

  float vx = evec[3*e+0], vy = evec[3*e+1], vz = evec[3*e+2];
  float nrm = sqrtf(vx*vx + vy*vy + vz*vz);
  float inv = 1.0f / (nrm + 1e-12f);
  float X = vx*inv, Yv = vy*inv, Z = vz*inv;

  const float S3 = 1.7320508075688772f;
  float Y0[1] = {1.0f};
  float Y1[3] = {Yv, Z, X};
  float Y2[5] = {S3*X*Yv, S3*Yv*Z, 0.5f*(3.0f*Z*Z - 1.0f), S3*X*Z, 0.5f*S3*(X*X - Yv*Yv)};

  const float* nfr = nf + (size_t)src * (4*CMUL);
  float x0[1] = { nfr[lane] };
  float x1[3] = { nfr[CMUL + 3*lane + 0],
                  nfr[CMUL + 3*lane + 1],
                  nfr[CMUL + 3*lane + 2] };

  const float* wr = g_w + (size_t)e * NW;
  float o0[1] = {0.f};
  float o1[3] = {0.f,0.f,0.f};
  float o2[5] = {0.f,0.f,0.f,0.f,0.f};

  // PATHS = [(0,0,0),(0,1,1),(0,2,2),(1,0,1),(1,1,0),(1,1,1),(1,1,2),(1,2,1),(1,2,2)]
  do_path<0,0,0>(wr[0*CMUL + lane], x0, Y0, o0);
  do_path<0,1,1>(wr[1*CMUL + lane], x0, Y1, o1);
  do_path<0,2,2>(wr[2*CMUL + lane], x0, Y2, o2);
  do_path<1,0,1>(wr[3*CMUL + lane], x1, Y0, o1);
  do_path<1,1,0>(wr[4*CMUL + lane], x1, Y1, o0);
  do_path<1,1,1>(wr[5*CMUL + lane], x1, Y1, o1);
  do_path<1,1,2>(wr[6*CMUL + lane], x1, Y1, o2);
  do_path<1,2,1>(wr[7*CMUL + lane], x1, Y2, o1);
  do_path<1,2,2>(wr[8*CMUL + lane], x1, Y2, o2);

  float* orow = out + (size_t)dst * NW;
  atomicAdd(orow + lane, o0[0]);
  #pragma unroll
  for (int c = 0; c < 3; ++c) atomicAdd(orow + CMUL + 3*lane + c, o1[c]);
  #pragma unroll
  for (int c = 0; c < 5; ++c) atomicAdd(orow + 4*CMUL + 5*lane + c, o2[c]);
}

// ============================================================
// Launch
// ============================================================
extern "C" void kernel_launch(void* const* d_in, const int* in_sizes, int n_in,
                              void* d_out, int out_size){
  const float* nf = (const float*)d_in[0];
  const float* ef = (const float*)d_in[1];
  const float* ev = (const float*)d_in[2];
  const int*   ei = (const int*)  d_in[3];
  const float* W0 = (const float*)d_in[4];
  const float* W1 = (const float*)d_in[5];
  const float* W2 = (const float*)d_in[6];
  float* out = (float*)d_out;

  int E = in_sizes[2] / 3;       // edge_vectors is (E, 3)
  if (E > MAX_E) E = MAX_E;

  cudaMemsetAsync(d_out, 0, (size_t)out_size * sizeof(float), 0);

  const int smem_bytes = SMEM_FLOATS * sizeof(float);
  cudaFuncSetAttribute(mlp_kernel, cudaFuncAttributeMaxDynamicSharedMemorySize, smem_bytes);

  int blocksA = (E + 255) / 256;
  mlp_kernel<<<blocksA, 256, smem_bytes>>>(ef, W0, W1, W2, E);

  int blocksB = (E * 32 + 255) / 256;
  tp_kernel<<<blocksB, 256>>>(nf, ev, ei, out, E);
}

// round 3
// speedup vs baseline: 1.0673x; 1.0673x over previous
#include <cuda_runtime.h>
#include <cstdint>
#include <cstddef>

// ============================================================
// Problem constants (fixed by the dataset)
// ============================================================
#define MAX_E   320000
#define NRBF    16
#define DH      64
#define NW      288      // 9 paths * 32 channels
#define CMUL    32

// scratch for per-edge MLP outputs w (E x 288), fp32
__device__ float g_w[(size_t)MAX_E * NW];

// ============================================================
// Compile-time Clebsch-Gordan (exact port of the reference math)
// ============================================================
struct CD { double re, im; };
__host__ __device__ constexpr CD cmulc(CD a, CD b){ return CD{a.re*b.re - a.im*b.im, a.re*b.im + a.im*b.re}; }
__host__ __device__ constexpr CD conjc(CD a){ return CD{a.re, -a.im}; }
__host__ __device__ constexpr double cfact(int n){ double r=1.0; for(int i=2;i<=n;++i) r*= (double)i; return r; }
__host__ __device__ constexpr double csqrt(double x){
  if (x <= 0.0) return 0.0;
  double r = x < 1.0 ? 1.0 : x;
  for (int i=0;i<200;++i) r = 0.5*(r + x/r);
  return r;
}
__host__ __device__ constexpr double cgc(int l1,int l2,int l3,int m1,int m2){
  int m3 = m1+m2;
  if (m3 < -l3 || m3 > l3) return 0.0;
  double pref = csqrt((double)(2*l3+1)*cfact(l1+l2-l3)*cfact(l1-l2+l3)*cfact(-l1+l2+l3)/cfact(l1+l2+l3+1));
  pref *= csqrt(cfact(l3+m3)*cfact(l3-m3)*cfact(l1-m1)*cfact(l1+m1)*cfact(l2-m2)*cfact(l2+m2));
  double s = 0.0;
  for (int k=0;k<=l1+l2-l3;++k){
    int a1=l1+l2-l3-k, a2=l1-m1-k, a3=l2+m2-k, a4=l3-l2+m1+k, a5=l3-l1-m2+k;
    if (a1<0||a2<0||a3<0||a4<0||a5<0) continue;
    double d = cfact(k)*cfact(a1)*cfact(a2)*cfact(a3)*cfact(a4)*cfact(a5);
    s += ((k&1)? -1.0 : 1.0)/d;
  }
  return pref*s;
}
struct UMat { CD u[5][5]; };
__host__ __device__ constexpr UMat makeU(int l){
  UMat U{};
  const double s = 1.0/csqrt(2.0);
  U.u[l][l] = CD{1.0, 0.0};
  for (int m=1;m<=l;++m){
    double sg = (m&1)? -1.0 : 1.0;
    U.u[l+m][l+m] = CD{sg*s, 0.0};
    U.u[l+m][l-m] = CD{s, 0.0};
    U.u[l-m][l-m] = CD{0.0, s};
    U.u[l-m][l+m] = CD{0.0, -sg*s};
  }
  return U;
}
struct CG3 { double v[5][5][5]; };
__host__ __device__ constexpr CG3 make_cg(int l1,int l2,int l3){
  UMat U1 = makeU(l1), U2 = makeU(l2), U3 = makeU(l3);
  int n1=2*l1+1, n2=2*l2+1, n3=2*l3+1;
  double tre[5][5][5] = {}, tim[5][5][5] = {};
  double mre=0.0, mim=0.0;
  for (int a=0;a<n1;++a) for (int b=0;b<n2;++b) for (int c=0;c<n3;++c){
    CD acc{0.0,0.0};
    for (int m=0;m<n1;++m) for (int n=0;n<n2;++n){
      int o = (m-l1)+(n-l2)+l3;
      if (o < 0 || o >= n3) continue;
      double cg = cgc(l1,l2,l3, m-l1, n-l2);
      if (cg == 0.0) continue;
      CD t = cmulc(cmulc(U1.u[a][m], U2.u[b][n]), conjc(U3.u[c][o]));
      acc.re += t.re*cg; acc.im += t.im*cg;
    }
    tre[a][b][c]=acc.re; tim[a][b][c]=acc.im;
    double ar = acc.re<0.0?-acc.re:acc.re;
    double ai = acc.im<0.0?-acc.im:acc.im;
    if (ar>mre) mre=ar;
    if (ai>mim) mim=ai;
  }
  CG3 R{};
  for (int a=0;a<n1;++a) for (int b=0;b<n2;++b) for (int c=0;c<n3;++c){
    double vv = (mre >= mim) ? tre[a][b][c] : tim[a][b][c];
    if (vv < 1e-12 && vv > -1e-12) vv = 0.0;
    R.v[a][b][c] = vv;
  }
  return R;
}

// ============================================================
// FFMA2: packed fp32 x2 FMA
// ============================================================
union F2U { float2 f; unsigned long long u; };
__device__ __forceinline__ float2 ffma2(float2 a, float2 b, float2 c){
  F2U A, B, C, D;
  A.f = a; B.f = b; C.f = c;
  asm("fma.rn.f32x2 %0, %1, %2, %3;" : "=l"(D.u) : "l"(A.u), "l"(B.u), "l"(C.u));
  return D.f;
}

// Fast silu: MUFU.EX2-based exp + MUFU.RCP-based division (no IEEE div sequence).
__device__ __forceinline__ float silu(float x){
  float ex = __expf(-x);
  return __fdividef(x, 1.0f + ex);
}

// ============================================================
// Kernel A: per-edge MLP  w = silu(silu(silu(ef@W0)@W1)@W2)
// One thread per edge; weights staged in shared memory.
// j-tile = 16 (8 packed float2 accumulators) to amortize operand packing.
// ============================================================
#define SMEM_FLOATS (NRBF*DH + DH*DH + DH*NW)   // 23552 floats = 94208 B

template<int IN, int OUT, bool TO_GLOBAL>
__device__ __forceinline__ void dense_silu(const float* __restrict__ x,
                                           const float* __restrict__ sW,
                                           float* __restrict__ y){
  #pragma unroll 1
  for (int j = 0; j < OUT; j += 16){
    float2 a0{0.f,0.f}, a1{0.f,0.f}, a2{0.f,0.f}, a3{0.f,0.f};
    float2 a4{0.f,0.f}, a5{0.f,0.f}, a6{0.f,0.f}, a7{0.f,0.f};
    #pragma unroll
    for (int k = 0; k < IN; ++k){
      float2 xx = make_float2(x[k], x[k]);
      const float4* wrow = reinterpret_cast<const float4*>(sW + k*OUT + j);
      float4 w0 = wrow[0];
      float4 w1 = wrow[1];
      float4 w2 = wrow[2];
      float4 w3 = wrow[3];
      a0 = ffma2(xx, make_float2(w0.x, w0.y), a0);
      a1 = ffma2(xx, make_float2(w0.z, w0.w), a1);
      a2 = ffma2(xx, make_float2(w1.x, w1.y), a2);
      a3 = ffma2(xx, make_float2(w1.z, w1.w), a3);
      a4 = ffma2(xx, make_float2(w2.x, w2.y), a4);
      a5 = ffma2(xx, make_float2(w2.z, w2.w), a5);
      a6 = ffma2(xx, make_float2(w3.x, w3.y), a6);
      a7 = ffma2(xx, make_float2(w3.z, w3.w), a7);
    }
    if (TO_GLOBAL){
      float4 o0 = make_float4(silu(a0.x), silu(a0.y), silu(a1.x), silu(a1.y));
      float4 o1 = make_float4(silu(a2.x), silu(a2.y), silu(a3.x), silu(a3.y));
      float4 o2 = make_float4(silu(a4.x), silu(a4.y), silu(a5.x), silu(a5.y));
      float4 o3 = make_float4(silu(a6.x), silu(a6.y), silu(a7.x), silu(a7.y));
      float4* yo = reinterpret_cast<float4*>(y + j);
      yo[0]=o0; yo[1]=o1; yo[2]=o2; yo[3]=o3;
    } else {
      y[j+ 0]=silu(a0.x); y[j+ 1]=silu(a0.y); y[j+ 2]=silu(a1.x); y[j+ 3]=silu(a1.y);
      y[j+ 4]=silu(a2.x); y[j+ 5]=silu(a2.y); y[j+ 6]=silu(a3.x); y[j+ 7]=silu(a3.y);
      y[j+ 8]=silu(a4.x); y[j+ 9]=silu(a4.y); y[j+10]=silu(a5.x); y[j+11]=silu(a5.y);
      y[j+12]=silu(a6.x); y[j+13]=silu(a6.y); y[j+14]=silu(a7.x); y[j+15]=silu(a7.y);
    }
  }
}

__global__ __launch_bounds__(256)
void mlp_kernel(const float* __restrict__ ef,
                const float* __restrict__ W0,
                const float* __restrict__ W1,
                const float* __restrict__ W2,
                int E){
  extern __shared__ float s[];
  float* sW0 = s;
  float* sW1 = s + NRBF*DH;
  float* sW2 = s + NRBF*DH + DH*DH;
  for (int i = threadIdx.x; i < NRBF*DH; i += blockDim.x) sW0[i] = W0[i];
  for (int i = threadIdx.x; i < DH*DH;   i += blockDim.x) sW1[i] = W1[i];
  for (int i = threadIdx.x; i < DH*NW;   i += blockDim.x) sW2[i] = W2[i];
  __syncthreads();

  int e = blockIdx.x * blockDim.x + threadIdx.x;
  if (e >= E) return;

  float x[NRBF];
  #pragma unroll
  for (int i = 0; i < NRBF/4; ++i){
    float4 t = reinterpret_cast<const float4*>(ef + (size_t)e*NRBF)[i];
    x[4*i+0]=t.x; x[4*i+1]=t.y; x[4*i+2]=t.z; x[4*i+3]=t.w;
  }
  float h1[DH];
  dense_silu<NRBF, DH, false>(x, sW0, h1);
  float h2[DH];
  dense_silu<DH, DH, false>(h1, sW1, h2);
  dense_silu<DH, NW, true>(h2, sW2, g_w + (size_t)e * NW);
}

// ============================================================
// Kernel B: tensor product + scatter-add.
// One warp per edge, one lane per channel u (CMUL == 32).
// ============================================================
template<int L1, int L2, int L3>
__device__ __forceinline__ void do_path(float wp, const float* x, const float* Y, float* o){
  constexpr CG3 cg = make_cg(L1, L2, L3);
  #pragma unroll
  for (int a = 0; a < 2*L1+1; ++a){
    float wx = wp * x[a];
    #pragma unroll
    for (int b = 0; b < 2*L2+1; ++b){
      #pragma unroll
      for (int c = 0; c < 2*L3+1; ++c){
        const float v = (float)cg.v[a][b][c];
        if (v != 0.0f){
          o[c] += wx * (v * Y[b]);
        }
      }
    }
  }
}

__global__ __launch_bounds__(256)
void tp_kernel(const float* __restrict__ nf,
               const float* __restrict__ evec,
               const int*   __restrict__ eidx,
               float* __restrict__ out,
               int E){
  int warp = (blockIdx.x * blockDim.x + threadIdx.x) >> 5;
  int lane = threadIdx.x & 31;
  if (warp >= E) return;
  int e = warp;

  int src = eidx[2*e+0];
  int dst = eidx[2*e+1];

  float vx = evec[3*e+0], vy = evec[3*e+1], vz = evec[3*e+2];
  float nrm = sqrtf(vx*vx + vy*vy + vz*vz);
  float inv = 1.0f / (nrm + 1e-12f);
  float X = vx*inv, Yv = vy*inv, Z = vz*inv;

  const float S3 = 1.7320508075688772f;
  float Y0[1] = {1.0f};
  float Y1[3] = {Yv, Z, X};
  float Y2[5] = {S3*X*Yv, S3*Yv*Z, 0.5f*(3.0f*Z*Z - 1.0f), S3*X*Z, 0.5f*S3*(X*X - Yv*Yv)};

  const float* nfr = nf + (size_t)src * (4*CMUL);
  float x0[1] = { nfr[lane] };
  float x1[3] = { nfr[CMUL + 3*lane + 0],
                  nfr[CMUL + 3*lane + 1],
                  nfr[CMUL + 3*lane + 2] };

  const float* wr = g_w + (size_t)e * NW;
  float o0[1] = {0.f};
  float o1[3] = {0.f,0.f,0.f};
  float o2[5] = {0.f,0.f,0.f,0.f,0.f};

  do_path<0,0,0>(wr[0*CMUL + lane], x0, Y0, o0);
  do_path<0,1,1>(wr[1*CMUL + lane], x0, Y1, o1);
  do_path<0,2,2>(wr[2*CMUL + lane], x0, Y2, o2);
  do_path<1,0,1>(wr[3*CMUL + lane], x1, Y0, o1);
  do_path<1,1,0>(wr[4*CMUL + lane], x1, Y1, o0);
  do_path<1,1,1>(wr[5*CMUL + lane], x1, Y1, o1);
  do_path<1,1,2>(wr[6*CMUL + lane], x1, Y1, o2);
  do_path<1,2,1>(wr[7*CMUL + lane], x1, Y2, o1);
  do_path<1,2,2>(wr[8*CMUL + lane], x1, Y2, o2);

  float* orow = out + (size_t)dst * NW;
  atomicAdd(orow + lane, o0[0]);
  #pragma unroll
  for (int c = 0; c < 3; ++c) atomicAdd(orow + CMUL + 3*lane + c, o1[c]);
  #pragma unroll
  for (int c = 0; c < 5; ++c) atomicAdd(orow + 4*CMUL + 5*lane + c, o2[c]);
}

// ============================================================
// Launch
// ============================================================
extern "C" void kernel_launch(void* const* d_in, const int* in_sizes, int n_in,
                              void* d_out, int out_size){
  const float* nf = (const float*)d_in[0];
  const float* ef = (const float*)d_in[1];
  const float* ev = (const float*)d_in[2];
  const int*   ei = (const int*)  d_in[3];
  const float* W0 = (const float*)d_in[4];
  const float* W1 = (const float*)d_in[5];
  const float* W2 = (const float*)d_in[6];
  float* out = (float*)d_out;

  int E = in_sizes[2] / 3;       // edge_vectors is (E, 3)
  if (E > MAX_E) E = MAX_E;

  cudaMemsetAsync(d_out, 0, (size_t)out_size * sizeof(float), 0);

  const int smem_bytes = SMEM_FLOATS * sizeof(float);
  cudaFuncSetAttribute(mlp_kernel, cudaFuncAttributeMaxDynamicSharedMemorySize, smem_bytes);

  int blocksA = (E + 255) / 256;
  mlp_kernel<<<blocksA, 256, smem_bytes>>>(ef, W0, W1, W2, E);

  int blocksB = (E * 32 + 255) / 256;
  tp_kernel<<<blocksB, 256>>>(nf, ev, ei, out, E);
}

// round 4
// speedup vs baseline: 1.2736x; 1.1932x over previous
#include <cuda_runtime.h>
#include <cstdint>
#include <cstddef>

// ============================================================
// Problem constants
// ============================================================
#define MAX_E   320000
#define NRBF    16
#define DH      64
#define NW      288
#define CMUL    32

#define TE      192      // edges per block in MLP
#define THREADS 432      // 13.5 warps

// scratch for per-edge MLP outputs w (E x 288), fp32
__device__ float g_w[(size_t)MAX_E * NW];

// ============================================================
// Compile-time Clebsch-Gordan (exact port of the reference math)
// ============================================================
struct CD { double re, im; };
__host__ __device__ constexpr CD cmulc(CD a, CD b){ return CD{a.re*b.re - a.im*b.im, a.re*b.im + a.im*b.re}; }
__host__ __device__ constexpr CD conjc(CD a){ return CD{a.re, -a.im}; }
__host__ __device__ constexpr double cfact(int n){ double r=1.0; for(int i=2;i<=n;++i) r*= (double)i; return r; }
__host__ __device__ constexpr double csqrt(double x){
  if (x <= 0.0) return 0.0;
  double r = x < 1.0 ? 1.0 : x;
  for (int i=0;i<200;++i) r = 0.5*(r + x/r);
  return r;
}
__host__ __device__ constexpr double cgc(int l1,int l2,int l3,int m1,int m2){
  int m3 = m1+m2;
  if (m3 < -l3 || m3 > l3) return 0.0;
  double pref = csqrt((double)(2*l3+1)*cfact(l1+l2-l3)*cfact(l1-l2+l3)*cfact(-l1+l2+l3)/cfact(l1+l2+l3+1));
  pref *= csqrt(cfact(l3+m3)*cfact(l3-m3)*cfact(l1-m1)*cfact(l1+m1)*cfact(l2-m2)*cfact(l2+m2));
  double s = 0.0;
  for (int k=0;k<=l1+l2-l3;++k){
    int a1=l1+l2-l3-k, a2=l1-m1-k, a3=l2+m2-k, a4=l3-l2+m1+k, a5=l3-l1-m2+k;
    if (a1<0||a2<0||a3<0||a4<0||a5<0) continue;
    double d = cfact(k)*cfact(a1)*cfact(a2)*cfact(a3)*cfact(a4)*cfact(a5);
    s += ((k&1)? -1.0 : 1.0)/d;
  }
  return pref*s;
}
struct UMat { CD u[5][5]; };
__host__ __device__ constexpr UMat makeU(int l){
  UMat U{};
  const double s = 1.0/csqrt(2.0);
  U.u[l][l] = CD{1.0, 0.0};
  for (int m=1;m<=l;++m){
    double sg = (m&1)? -1.0 : 1.0;
    U.u[l+m][l+m] = CD{sg*s, 0.0};
    U.u[l+m][l-m] = CD{s, 0.0};
    U.u[l-m][l-m] = CD{0.0, s};
    U.u[l-m][l+m] = CD{0.0, -sg*s};
  }
  return U;
}
struct CG3 { double v[5][5][5]; };
__host__ __device__ constexpr CG3 make_cg(int l1,int l2,int l3){
  UMat U1 = makeU(l1), U2 = makeU(l2), U3 = makeU(l3);
  int n1=2*l1+1, n2=2*l2+1, n3=2*l3+1;
  double tre[5][5][5] = {}, tim[5][5][5] = {};
  double mre=0.0, mim=0.0;
  for (int a=0;a<n1;++a) for (int b=0;b<n2;++b) for (int c=0;c<n3;++c){
    CD acc{0.0,0.0};
    for (int m=0;m<n1;++m) for (int n=0;n<n2;++n){
      int o = (m-l1)+(n-l2)+l3;
      if (o < 0 || o >= n3) continue;
      double cg = cgc(l1,l2,l3, m-l1, n-l2);
      if (cg == 0.0) continue;
      CD t = cmulc(cmulc(U1.u[a][m], U2.u[b][n]), conjc(U3.u[c][o]));
      acc.re += t.re*cg; acc.im += t.im*cg;
    }
    tre[a][b][c]=acc.re; tim[a][b][c]=acc.im;
    double ar = acc.re<0.0?-acc.re:acc.re;
    double ai = acc.im<0.0?-acc.im:acc.im;
    if (ar>mre) mre=ar;
    if (ai>mim) mim=ai;
  }
  CG3 R{};
  for (int a=0;a<n1;++a) for (int b=0;b<n2;++b) for (int c=0;c<n3;++c){
    double vv = (mre >= mim) ? tre[a][b][c] : tim[a][b][c];
    if (vv < 1e-12 && vv > -1e-12) vv = 0.0;
    R.v[a][b][c] = vv;
  }
  return R;
}

// ============================================================
// FFMA2 + fast silu
// ============================================================
union F2U { float2 f; unsigned long long u; };
__device__ __forceinline__ float2 ffma2(float2 a, float2 b, float2 c){
  F2U A, B, C, D;
  A.f = a; B.f = b; C.f = c;
  asm("fma.rn.f32x2 %0, %1, %2, %3;" : "=l"(D.u) : "l"(A.u), "l"(B.u), "l"(C.u));
  return D.f;
}
__device__ __forceinline__ float silu(float x){
  return __fdividef(x, 1.0f + __expf(-x));
}

// ============================================================
// MLP as block-tiled GEMM.
// smem: W0|W1|W2 (23552 f) + sX [16][192] + sH1 [64][192] + sH2 [64][192]
// Activations stored k-major [k][e] so the GEMM inner loop reads 8/4
// consecutive edges per LDS.128.
// ============================================================
#define SMEM_FLOATS (NRBF*DH + DH*DH + DH*NW + NRBF*TE + DH*TE + DH*TE)  // 51200 floats = 200KB

// layer for OUT=64: thread tile 4 edges x 8 outputs; 384 active threads.
template<int K>
__device__ __forceinline__ void layer64(const float* __restrict__ sIn,   // [K][TE]
                                        const float* __restrict__ sW,    // [K][64]
                                        float* __restrict__ sOut,        // [64][TE]
                                        int t){
  if (t >= 384) return;
  int et = t % 48, jt = t / 48;
  int e0 = et * 4, j0 = jt * 8;
  float2 acc[4][4];
  #pragma unroll
  for (int i=0;i<4;++i)
    #pragma unroll
    for (int j=0;j<4;++j) acc[i][j] = make_float2(0.f, 0.f);

  #pragma unroll 8
  for (int k = 0; k < K; ++k){
    float4 a  = *reinterpret_cast<const float4*>(sIn + k*TE + e0);
    float4 w0 = *reinterpret_cast<const float4*>(sW + k*64 + j0);
    float4 w1 = *reinterpret_cast<const float4*>(sW + k*64 + j0 + 4);
    float2 wp[4] = { make_float2(w0.x,w0.y), make_float2(w0.z,w0.w),
                     make_float2(w1.x,w1.y), make_float2(w1.z,w1.w) };
    float av[4] = { a.x, a.y, a.z, a.w };
    #pragma unroll
    for (int i=0;i<4;++i){
      float2 ai = make_float2(av[i], av[i]);
      #pragma unroll
      for (int j=0;j<4;++j) acc[i][j] = ffma2(ai, wp[j], acc[i][j]);
    }
  }
  #pragma unroll
  for (int jj=0;jj<4;++jj){
    int j = j0 + 2*jj;
    float4 lo = make_float4(silu(acc[0][jj].x), silu(acc[1][jj].x),
                            silu(acc[2][jj].x), silu(acc[3][jj].x));
    float4 hi = make_float4(silu(acc[0][jj].y), silu(acc[1][jj].y),
                            silu(acc[2][jj].y), silu(acc[3][jj].y));
    *reinterpret_cast<float4*>(sOut + (size_t)j*TE + e0)     = lo;
    *reinterpret_cast<float4*>(sOut + (size_t)(j+1)*TE + e0) = hi;
  }
}

__global__ __launch_bounds__(THREADS)
void mlp_kernel(const float* __restrict__ ef,
                const float* __restrict__ W0,
                const float* __restrict__ W1,
                const float* __restrict__ W2,
                int E){
  extern __shared__ float s[];
  float* sW0 = s;                       // 16*64
  float* sW1 = sW0 + NRBF*DH;           // 64*64
  float* sW2 = sW1 + DH*DH;             // 64*288
  float* sX  = sW2 + DH*NW;             // 16*TE
  float* sH1 = sX + NRBF*TE;            // 64*TE
  float* sH2 = sH1 + DH*TE;             // 64*TE

  int t = threadIdx.x;

  // stage weights (vectorized)
  {
    const float4* w = (const float4*)W0; float4* d = (float4*)sW0;
    for (int i=t; i<NRBF*DH/4; i+=THREADS) d[i] = w[i];
    w = (const float4*)W1; d = (float4*)sW1;
    for (int i=t; i<DH*DH/4; i+=THREADS) d[i] = w[i];
    w = (const float4*)W2; d = (float4*)sW2;
    for (int i=t; i<DH*NW/4; i+=THREADS) d[i] = w[i];
  }

  int eBase = blockIdx.x * TE;

  // stage inputs transposed: sX[k][e]
  if (t < TE){
    int e = eBase + t;
    if (e >= E) e = E - 1;
    const float4* src = reinterpret_cast<const float4*>(ef + (size_t)e * NRBF);
    float4 v0 = src[0], v1 = src[1], v2 = src[2], v3 = src[3];
    float vv[16] = { v0.x,v0.y,v0.z,v0.w, v1.x,v1.y,v1.z,v1.w,
                     v2.x,v2.y,v2.z,v2.w, v3.x,v3.y,v3.z,v3.w };
    #pragma unroll
    for (int k=0;k<NRBF;++k) sX[k*TE + t] = vv[k];
  }
  __syncthreads();

  layer64<NRBF>(sX, sW0, sH1, t);
  __syncthreads();
  layer64<DH>(sH1, sW1, sH2, t);
  __syncthreads();

  // Layer 3: [TE x 64] @ [64 x 288] -> g_w. Thread tile 8 edges x 8 outs.
  // 24 e-tiles x 36 j-tiles = 864 tiles = 2 per thread, exact.
  int et = t % 24;
  int jtb = t / 24;      // 0..17
  #pragma unroll 1
  for (int rep = 0; rep < 2; ++rep){
    int jt = jtb + rep * 18;
    int e0 = et * 8, j0 = jt * 8;
    float2 acc[8][4];
    #pragma unroll
    for (int i=0;i<8;++i)
      #pragma unroll
      for (int j=0;j<4;++j) acc[i][j] = make_float2(0.f,0.f);

    #pragma unroll 8
    for (int k = 0; k < DH; ++k){
      float4 a0 = *reinterpret_cast<const float4*>(sH2 + k*TE + e0);
      float4 a1 = *reinterpret_cast<const float4*>(sH2 + k*TE + e0 + 4);
      float4 w0 = *reinterpret_cast<const float4*>(sW2 + k*NW + j0);
      float4 w1 = *reinterpret_cast<const float4*>(sW2 + k*NW + j0 + 4);
      float2 wp[4] = { make_float2(w0.x,w0.y), make_float2(w0.z,w0.w),
                       make_float2(w1.x,w1.y), make_float2(w1.z,w1.w) };
      float av[8] = { a0.x,a0.y,a0.z,a0.w, a1.x,a1.y,a1.z,a1.w };
      #pragma unroll
      for (int i=0;i<8;++i){
        float2 ai = make_float2(av[i], av[i]);
        #pragma unroll
        for (int j=0;j<4;++j) acc[i][j] = ffma2(ai, wp[j], acc[i][j]);
      }
    }
    // epilogue: silu + store rows of g_w
    #pragma unroll
    for (int i=0;i<8;++i){
      int e = eBase + e0 + i;
      if (e < E){
        float4 lo = make_float4(silu(acc[i][0].x), silu(acc[i][0].y),
                                silu(acc[i][1].x), silu(acc[i][1].y));
        float4 hi = make_float4(silu(acc[i][2].x), silu(acc[i][2].y),
                                silu(acc[i][3].x), silu(acc[i][3].y));
        float* row = g_w + (size_t)e * NW + j0;
        *reinterpret_cast<float4*>(row)     = lo;
        *reinterpret_cast<float4*>(row + 4) = hi;
      }
    }
  }
}

// ============================================================
// Kernel B: tensor product + scatter-add (unchanged).
// ============================================================
template<int L1, int L2, int L3>
__device__ __forceinline__ void do_path(float wp, const float* x, const float* Y, float* o){
  constexpr CG3 cg = make_cg(L1, L2, L3);
  #pragma unroll
  for (int a = 0; a < 2*L1+1; ++a){
    float wx = wp * x[a];
    #pragma unroll
    for (int b = 0; b < 2*L2+1; ++b){
      #pragma unroll
      for (int c = 0; c < 2*L3+1; ++c){
        const float v = (float)cg.v[a][b][c];
        if (v != 0.0f){
          o[c] += wx * (v * Y[b]);
        }
      }
    }
  }
}

__global__ __launch_bounds__(256)
void tp_kernel(const float* __restrict__ nf,
               const float* __restrict__ evec,
               const int*   __restrict__ eidx,
               float* __restrict__ out,
               int E){
  int warp = (blockIdx.x * blockDim.x + threadIdx.x) >> 5;
  int lane = threadIdx.x & 31;
  if (warp >= E) return;
  int e = warp;

  int src = eidx[2*e+0];
  int dst = eidx[2*e+1];

  float vx = evec[3*e+0], vy = evec[3*e+1], vz = evec[3*e+2];
  float nrm = sqrtf(vx*vx + vy*vy + vz*vz);
  float inv = 1.0f / (nrm + 1e-12f);
  float X = vx*inv, Yv = vy*inv, Z = vz*inv;

  const float S3 = 1.7320508075688772f;
  float Y0[1] = {1.0f};
  float Y1[3] = {Yv, Z, X};
  float Y2[5] = {S3*X*Yv, S3*Yv*Z, 0.5f*(3.0f*Z*Z - 1.0f), S3*X*Z, 0.5f*S3*(X*X - Yv*Yv)};

  const float* nfr = nf + (size_t)src * (4*CMUL);
  float x0[1] = { nfr[lane] };
  float x1[3] = { nfr[CMUL + 3*lane + 0],
                  nfr[CMUL + 3*lane + 1],
                  nfr[CMUL + 3*lane + 2] };

  const float* wr = g_w + (size_t)e * NW;
  float o0[1] = {0.f};
  float o1[3] = {0.f,0.f,0.f};
  float o2[5] = {0.f,0.f,0.f,0.f,0.f};

  do_path<0,0,0>(wr[0*CMUL + lane], x0, Y0, o0);
  do_path<0,1,1>(wr[1*CMUL + lane], x0, Y1, o1);
  do_path<0,2,2>(wr[2*CMUL + lane], x0, Y2, o2);
  do_path<1,0,1>(wr[3*CMUL + lane], x1, Y0, o1);
  do_path<1,1,0>(wr[4*CMUL + lane], x1, Y1, o0);
  do_path<1,1,1>(wr[5*CMUL + lane], x1, Y1, o1);
  do_path<1,1,2>(wr[6*CMUL + lane], x1, Y1, o2);
  do_path<1,2,1>(wr[7*CMUL + lane], x1, Y2, o1);
  do_path<1,2,2>(wr[8*CMUL + lane], x1, Y2, o2);

  float* orow = out + (size_t)dst * NW;
  atomicAdd(orow + lane, o0[0]);
  #pragma unroll
  for (int c = 0; c < 3; ++c) atomicAdd(orow + CMUL + 3*lane + c, o1[c]);
  #pragma unroll
  for (int c = 0; c < 5; ++c) atomicAdd(orow + 4*CMUL + 5*lane + c, o2[c]);
}

// ============================================================
// Launch
// ============================================================
extern "C" void kernel_launch(void* const* d_in, const int* in_sizes, int n_in,
                              void* d_out, int out_size){
  const float* nf = (const float*)d_in[0];
  const float* ef = (const float*)d_in[1];
  const float* ev = (const float*)d_in[2];
  const int*   ei = (const int*)  d_in[3];
  const float* W0 = (const float*)d_in[4];
  const float* W1 = (const float*)d_in[5];
  const float* W2 = (const float*)d_in[6];
  float* out = (float*)d_out;

  int E = in_sizes[2] / 3;
  if (E > MAX_E) E = MAX_E;

  cudaMemsetAsync(d_out, 0, (size_t)out_size * sizeof(float), 0);

  const int smem_bytes = SMEM_FLOATS * sizeof(float);   // 204800 B
  cudaFuncSetAttribute(mlp_kernel, cudaFuncAttributeMaxDynamicSharedMemorySize, smem_bytes);

  int blocksA = (E + TE - 1) / TE;
  mlp_kernel<<<blocksA, THREADS, smem_bytes>>>(ef, W0, W1, W2, E);

  int blocksB = (E * 32 + 255) / 256;
  tp_kernel<<<blocksB, 256>>>(nf, ev, ei, out, E);
}

// round 5
// speedup vs baseline: 1.7421x; 1.3679x over previous
#include <cuda_runtime.h>
#include <cstdint>
#include <cstddef>

// ============================================================
// Problem constants
// ============================================================
#define MAX_E   320000
#define NRBF    16
#define DH      64
#define NW      288
#define CMUL    32

#define TE      256      // edges per block in MLP
#define STRIDE  260      // padded activation row stride (floats)
#define THREADS 384      // 12 warps
#define NWARP   12

// scratch for per-edge MLP outputs w (E x 288), fp32
__device__ float g_w[(size_t)MAX_E * NW];

// ============================================================
// Compile-time Clebsch-Gordan (exact port of the reference math)
// ============================================================
struct CD { double re, im; };
__host__ __device__ constexpr CD cmulc(CD a, CD b){ return CD{a.re*b.re - a.im*b.im, a.re*b.im + a.im*b.re}; }
__host__ __device__ constexpr CD conjc(CD a){ return CD{a.re, -a.im}; }
__host__ __device__ constexpr double cfact(int n){ double r=1.0; for(int i=2;i<=n;++i) r*= (double)i; return r; }
__host__ __device__ constexpr double csqrt(double x){
  if (x <= 0.0) return 0.0;
  double r = x < 1.0 ? 1.0 : x;
  for (int i=0;i<200;++i) r = 0.5*(r + x/r);
  return r;
}
__host__ __device__ constexpr double cgc(int l1,int l2,int l3,int m1,int m2){
  int m3 = m1+m2;
  if (m3 < -l3 || m3 > l3) return 0.0;
  double pref = csqrt((double)(2*l3+1)*cfact(l1+l2-l3)*cfact(l1-l2+l3)*cfact(-l1+l2+l3)/cfact(l1+l2+l3+1));
  pref *= csqrt(cfact(l3+m3)*cfact(l3-m3)*cfact(l1-m1)*cfact(l1+m1)*cfact(l2-m2)*cfact(l2+m2));
  double s = 0.0;
  for (int k=0;k<=l1+l2-l3;++k){
    int a1=l1+l2-l3-k, a2=l1-m1-k, a3=l2+m2-k, a4=l3-l2+m1+k, a5=l3-l1-m2+k;
    if (a1<0||a2<0||a3<0||a4<0||a5<0) continue;
    double d = cfact(k)*cfact(a1)*cfact(a2)*cfact(a3)*cfact(a4)*cfact(a5);
    s += ((k&1)? -1.0 : 1.0)/d;
  }
  return pref*s;
}
struct UMat { CD u[5][5]; };
__host__ __device__ constexpr UMat makeU(int l){
  UMat U{};
  const double s = 1.0/csqrt(2.0);
  U.u[l][l] = CD{1.0, 0.0};
  for (int m=1;m<=l;++m){
    double sg = (m&1)? -1.0 : 1.0;
    U.u[l+m][l+m] = CD{sg*s, 0.0};
    U.u[l+m][l-m] = CD{s, 0.0};
    U.u[l-m][l-m] = CD{0.0, s};
    U.u[l-m][l+m] = CD{0.0, -sg*s};
  }
  return U;
}
struct CG3 { double v[5][5][5]; };
__host__ __device__ constexpr CG3 make_cg(int l1,int l2,int l3){
  UMat U1 = makeU(l1), U2 = makeU(l2), U3 = makeU(l3);
  int n1=2*l1+1, n2=2*l2+1, n3=2*l3+1;
  double tre[5][5][5] = {}, tim[5][5][5] = {};
  double mre=0.0, mim=0.0;
  for (int a=0;a<n1;++a) for (int b=0;b<n2;++b) for (int c=0;c<n3;++c){
    CD acc{0.0,0.0};
    for (int m=0;m<n1;++m) for (int n=0;n<n2;++n){
      int o = (m-l1)+(n-l2)+l3;
      if (o < 0 || o >= n3) continue;
      double cg = cgc(l1,l2,l3, m-l1, n-l2);
      if (cg == 0.0) continue;
      CD t = cmulc(cmulc(U1.u[a][m], U2.u[b][n]), conjc(U3.u[c][o]));
      acc.re += t.re*cg; acc.im += t.im*cg;
    }
    tre[a][b][c]=acc.re; tim[a][b][c]=acc.im;
    double ar = acc.re<0.0?-acc.re:acc.re;
    double ai = acc.im<0.0?-acc.im:acc.im;
    if (ar>mre) mre=ar;
    if (ai>mim) mim=ai;
  }
  CG3 R{};
  for (int a=0;a<n1;++a) for (int b=0;b<n2;++b) for (int c=0;c<n3;++c){
    double vv = (mre >= mim) ? tre[a][b][c] : tim[a][b][c];
    if (vv < 1e-12 && vv > -1e-12) vv = 0.0;
    R.v[a][b][c] = vv;
  }
  return R;
}

// ============================================================
// FFMA2 + fast silu
// ============================================================
union F2U { float2 f; unsigned long long u; };
__device__ __forceinline__ float2 ffma2(float2 a, float2 b, float2 c){
  F2U A, B, C, D;
  A.f = a; B.f = b; C.f = c;
  asm("fma.rn.f32x2 %0, %1, %2, %3;" : "=l"(D.u) : "l"(A.u), "l"(B.u), "l"(C.u));
  return D.f;
}
__device__ __forceinline__ float silu(float x){
  return __fdividef(x, 1.0f + __expf(-x));
}

// ============================================================
// MLP: block-tiled GEMM chain, warp tile 32e x 32j, thread tile 8e x 4j,
// edges packed in float2. Lane layout: eg = lane>>3 (4 e-groups of 8),
// jg = lane&7 (8 j-groups of 4). All duplicate smem reads are intra-warp
// broadcasts (free); unique traffic per k-iter per warp = 3 x 128B.
// ============================================================
#define SMEM_FLOATS (NRBF*DH + DH*DH + DH*NW + 2*DH*STRIDE)  // 23552 + 33280 = 56832

// One GEMM layer over warp tiles. OUT in {64, 288}. K in {16, 64}.
// If TOGMEM: apply silu and write rows of g_w; else silu and write sOut[j][e].
template<int K, int OUT, bool TOGMEM>
__device__ __forceinline__ void gemm_layer(const float* __restrict__ sIn,   // [K][STRIDE]
                                           const float* __restrict__ sW,    // [K][OUT]
                                           float* __restrict__ sOut,        // [OUT][STRIDE] (if !TOGMEM)
                                           int eBase, int E,
                                           int warp, int lane){
  const int JT = OUT / 32;          // j warp-tiles
  const int NT = JT * (TE / 32);    // total warp tiles
  int jg = lane & 7, eg = lane >> 3;

  for (int tile = warp; tile < NT; tile += NWARP){
    int jt = tile % JT, et = tile / JT;
    int j0 = jt*32 + jg*4;
    int e0 = et*32 + eg*8;

    float2 acc[4][4];
    #pragma unroll
    for (int i=0;i<4;++i)
      #pragma unroll
      for (int j=0;j<4;++j) acc[i][j] = make_float2(0.f,0.f);

    #pragma unroll 8
    for (int k = 0; k < K; ++k){
      const float* aR = sIn + k*STRIDE + e0;
      float4 a0 = *reinterpret_cast<const float4*>(aR);      // edges e0..e0+3
      float4 a1 = *reinterpret_cast<const float4*>(aR + 4);  // edges e0+4..e0+7
      float4 wv = *reinterpret_cast<const float4*>(sW + k*OUT + j0);
      float2 ap[4] = { make_float2(a0.x,a0.y), make_float2(a0.z,a0.w),
                       make_float2(a1.x,a1.y), make_float2(a1.z,a1.w) };
      float2 wp[4] = { make_float2(wv.x,wv.x), make_float2(wv.y,wv.y),
                       make_float2(wv.z,wv.z), make_float2(wv.w,wv.w) };
      #pragma unroll
      for (int ep=0; ep<4; ++ep){
        #pragma unroll
        for (int jj=0; jj<4; ++jj)
          acc[ep][jj] = ffma2(ap[ep], wp[jj], acc[ep][jj]);
      }
    }

    if (!TOGMEM){
      // write transposed: sOut[j][e], e-contiguous per column -> 2 STS.128 per jj
      #pragma unroll
      for (int jj=0; jj<4; ++jj){
        float* col = sOut + (size_t)(j0+jj)*STRIDE + e0;
        float4 lo = make_float4(silu(acc[0][jj].x), silu(acc[0][jj].y),
                                silu(acc[1][jj].x), silu(acc[1][jj].y));
        float4 hi = make_float4(silu(acc[2][jj].x), silu(acc[2][jj].y),
                                silu(acc[3][jj].x), silu(acc[3][jj].y));
        *reinterpret_cast<float4*>(col)     = lo;
        *reinterpret_cast<float4*>(col + 4) = hi;
      }
    } else {
      // write g_w rows: per edge, j0..j0+3 contiguous -> coalesced 128B per row-chunk
      #pragma unroll
      for (int ep=0; ep<4; ++ep){
        int ea = eBase + e0 + 2*ep;
        if (ea < E){
          float4 v = make_float4(silu(acc[ep][0].x), silu(acc[ep][1].x),
                                 silu(acc[ep][2].x), silu(acc[ep][3].x));
          *reinterpret_cast<float4*>(g_w + (size_t)ea*NW + j0) = v;
        }
        if (ea + 1 < E){
          float4 v = make_float4(silu(acc[ep][0].y), silu(acc[ep][1].y),
                                 silu(acc[ep][2].y), silu(acc[ep][3].y));
          *reinterpret_cast<float4*>(g_w + (size_t)(ea+1)*NW + j0) = v;
        }
      }
    }
  }
}

__global__ __launch_bounds__(THREADS)
void mlp_kernel(const float* __restrict__ ef,
                const float* __restrict__ W0,
                const float* __restrict__ W1,
                const float* __restrict__ W2,
                int E){
  extern __shared__ float s[];
  float* sW0 = s;                        // 16*64
  float* sW1 = sW0 + NRBF*DH;            // 64*64
  float* sW2 = sW1 + DH*DH;              // 64*288
  float* regA = sW2 + DH*NW;             // 64*STRIDE  (sX rows 0..15, later sH2)
  float* regB = regA + DH*STRIDE;        // 64*STRIDE  (sH1)

  int t = threadIdx.x;
  int warp = t >> 5, lane = t & 31;

  // stage weights (vectorized)
  {
    const float4* w = (const float4*)W0; float4* d = (float4*)sW0;
    for (int i=t; i<NRBF*DH/4; i+=THREADS) d[i] = w[i];
    w = (const float4*)W1; d = (float4*)sW1;
    for (int i=t; i<DH*DH/4; i+=THREADS) d[i] = w[i];
    w = (const float4*)W2; d = (float4*)sW2;
    for (int i=t; i<DH*NW/4; i+=THREADS) d[i] = w[i];
  }

  int eBase = blockIdx.x * TE;

  // stage inputs transposed: regA[k][e]
  if (t < TE){
    int e = eBase + t;
    if (e >= E) e = E - 1;
    const float4* src = reinterpret_cast<const float4*>(ef + (size_t)e * NRBF);
    float4 v0 = src[0], v1 = src[1], v2 = src[2], v3 = src[3];
    float vv[16] = { v0.x,v0.y,v0.z,v0.w, v1.x,v1.y,v1.z,v1.w,
                     v2.x,v2.y,v2.z,v2.w, v3.x,v3.y,v3.z,v3.w };
    #pragma unroll
    for (int k=0;k<NRBF;++k) regA[k*STRIDE + t] = vv[k];
  }
  __syncthreads();

  gemm_layer<NRBF, DH, false>(regA, sW0, regB, eBase, E, warp, lane);  // sX -> sH1
  __syncthreads();
  gemm_layer<DH, DH, false>(regB, sW1, regA, eBase, E, warp, lane);    // sH1 -> sH2 (over sX)
  __syncthreads();
  gemm_layer<DH, NW, true>(regA, sW2, nullptr, eBase, E, warp, lane);  // sH2 -> g_w
}

// ============================================================
// Kernel B: tensor product + smem-staged coalesced scatter-add.
// One warp per edge, one lane per channel u (CMUL == 32).
// ============================================================
template<int L1, int L2, int L3>
__device__ __forceinline__ void do_path(float wp, const float* x, const float* Y, float* o){
  constexpr CG3 cg = make_cg(L1, L2, L3);
  #pragma unroll
  for (int a = 0; a < 2*L1+1; ++a){
    float wx = wp * x[a];
    #pragma unroll
    for (int b = 0; b < 2*L2+1; ++b){
      #pragma unroll
      for (int c = 0; c < 2*L3+1; ++c){
        const float v = (float)cg.v[a][b][c];
        if (v != 0.0f){
          o[c] += wx * (v * Y[b]);
        }
      }
    }
  }
}

__global__ __launch_bounds__(256)
void tp_kernel(const float* __restrict__ nf,
               const float* __restrict__ evec,
               const int*   __restrict__ eidx,
               float* __restrict__ out,
               int E){
  __shared__ float sb[8][NW];   // per-warp message staging
  int warp = (blockIdx.x * blockDim.x + threadIdx.x) >> 5;
  int wi = (threadIdx.x >> 5);
  int lane = threadIdx.x & 31;
  if (warp >= E) return;
  int e = warp;

  int src = eidx[2*e+0];
  int dst = eidx[2*e+1];

  float vx = evec[3*e+0], vy = evec[3*e+1], vz = evec[3*e+2];
  float nrm = sqrtf(vx*vx + vy*vy + vz*vz);
  float inv = 1.0f / (nrm + 1e-12f);
  float X = vx*inv, Yv = vy*inv, Z = vz*inv;

  const float S3 = 1.7320508075688772f;
  float Y0[1] = {1.0f};
  float Y1[3] = {Yv, Z, X};
  float Y2[5] = {S3*X*Yv, S3*Yv*Z, 0.5f*(3.0f*Z*Z - 1.0f), S3*X*Z, 0.5f*S3*(X*X - Yv*Yv)};

  const float* nfr = nf + (size_t)src * (4*CMUL);
  float x0[1] = { nfr[lane] };
  float x1[3] = { nfr[CMUL + 3*lane + 0],
                  nfr[CMUL + 3*lane + 1],
                  nfr[CMUL + 3*lane + 2] };

  const float* wr = g_w + (size_t)e * NW;
  float o0[1] = {0.f};
  float o1[3] = {0.f,0.f,0.f};
  float o2[5] = {0.f,0.f,0.f,0.f,0.f};

  do_path<0,0,0>(wr[0*CMUL + lane], x0, Y0, o0);
  do_path<0,1,1>(wr[1*CMUL + lane], x0, Y1, o1);
  do_path<0,2,2>(wr[2*CMUL + lane], x0, Y2, o2);
  do_path<1,0,1>(wr[3*CMUL + lane], x1, Y0, o1);
  do_path<1,1,0>(wr[4*CMUL + lane], x1, Y1, o0);
  do_path<1,1,1>(wr[5*CMUL + lane], x1, Y1, o1);
  do_path<1,1,2>(wr[6*CMUL + lane], x1, Y1, o2);
  do_path<1,2,1>(wr[7*CMUL + lane], x1, Y2, o1);
  do_path<1,2,2>(wr[8*CMUL + lane], x1, Y2, o2);

  // stage message into smem (strides 1/3/5 are bank-conflict-free)
  sb[wi][lane] = o0[0];
  #pragma unroll
  for (int c = 0; c < 3; ++c) sb[wi][CMUL + 3*lane + c] = o1[c];
  #pragma unroll
  for (int c = 0; c < 5; ++c) sb[wi][4*CMUL + 5*lane + c] = o2[c];
  __syncwarp();

  // 9 fully-coalesced atomic adds (dst is warp-uniform)
  float* orow = out + (size_t)dst * NW;
  #pragma unroll
  for (int p = 0; p < 9; ++p)
    atomicAdd(orow + p*32 + lane, sb[wi][p*32 + lane]);
}

// ============================================================
// Launch
// ============================================================
extern "C" void kernel_launch(void* const* d_in, const int* in_sizes, int n_in,
                              void* d_out, int out_size){
  const float* nf = (const float*)d_in[0];
  const float* ef = (const float*)d_in[1];
  const float* ev = (const float*)d_in[2];
  const int*   ei = (const int*)  d_in[3];
  const float* W0 = (const float*)d_in[4];
  const float* W1 = (const float*)d_in[5];
  const float* W2 = (const float*)d_in[6];
  float* out = (float*)d_out;

  int E = in_sizes[2] / 3;
  if (E > MAX_E) E = MAX_E;

  cudaMemsetAsync(d_out, 0, (size_t)out_size * sizeof(float), 0);

  const int smem_bytes = SMEM_FLOATS * sizeof(float);   // 227328 B
  cudaFuncSetAttribute(mlp_kernel, cudaFuncAttributeMaxDynamicSharedMemorySize, smem_bytes);

  int blocksA = (E + TE - 1) / TE;
  mlp_kernel<<<blocksA, THREADS, smem_bytes>>>(ef, W0, W1, W2, E);

  int blocksB = (E * 32 + 255) / 256;
  tp_kernel<<<blocksB, 256>>>(nf, ev, ei, out, E);
}

// round 7
// speedup vs baseline: 2.5947x; 1.4894x over previous
#include <cuda_runtime.h>
#include <cuda_bf16.h>
#include <cstdint>
#include <cstddef>

// ============================================================
// Problem constants
// ============================================================
#define MAX_E   320000
#define NRBF    16
#define DH      64
#define NW      288
#define CMUL    32

// scratch for per-edge MLP outputs w (E x 288), fp32
__device__ float g_w[(size_t)MAX_E * NW];

// ============================================================
// Compile-time Clebsch-Gordan (exact port of the reference math)
// ============================================================
struct CD { double re, im; };
__host__ __device__ constexpr CD cmulc(CD a, CD b){ return CD{a.re*b.re - a.im*b.im, a.re*b.im + a.im*b.re}; }
__host__ __device__ constexpr CD conjc(CD a){ return CD{a.re, -a.im}; }
__host__ __device__ constexpr double cfact(int n){ double r=1.0; for(int i=2;i<=n;++i) r*= (double)i; return r; }
__host__ __device__ constexpr double csqrt(double x){
  if (x <= 0.0) return 0.0;
  double r = x < 1.0 ? 1.0 : x;
  for (int i=0;i<200;++i) r = 0.5*(r + x/r);
  return r;
}
__host__ __device__ constexpr double cgc(int l1,int l2,int l3,int m1,int m2){
  int m3 = m1+m2;
  if (m3 < -l3 || m3 > l3) return 0.0;
  double pref = csqrt((double)(2*l3+1)*cfact(l1+l2-l3)*cfact(l1-l2+l3)*cfact(-l1+l2+l3)/cfact(l1+l2+l3+1));
  pref *= csqrt(cfact(l3+m3)*cfact(l3-m3)*cfact(l1-m1)*cfact(l1+m1)*cfact(l2-m2)*cfact(l2+m2));
  double s = 0.0;
  for (int k=0;k<=l1+l2-l3;++k){
    int a1=l1+l2-l3-k, a2=l1-m1-k, a3=l2+m2-k, a4=l3-l2+m1+k, a5=l3-l1-m2+k;
    if (a1<0||a2<0||a3<0||a4<0||a5<0) continue;
    double d = cfact(k)*cfact(a1)*cfact(a2)*cfact(a3)*cfact(a4)*cfact(a5);
    s += ((k&1)? -1.0 : 1.0)/d;
  }
  return pref*s;
}
struct UMat { CD u[5][5]; };
__host__ __device__ constexpr UMat makeU(int l){
  UMat U{};
  const double s = 1.0/csqrt(2.0);
  U.u[l][l] = CD{1.0, 0.0};
  for (int m=1;m<=l;++m){
    double sg = (m&1)? -1.0 : 1.0;
    U.u[l+m][l+m] = CD{sg*s, 0.0};
    U.u[l+m][l-m] = CD{s, 0.0};
    U.u[l-m][l-m] = CD{0.0, s};
    U.u[l-m][l+m] = CD{0.0, -sg*s};
  }
  return U;
}
struct CG3 { double v[5][5][5]; };
__host__ __device__ constexpr CG3 make_cg(int l1,int l2,int l3){
  UMat U1 = makeU(l1), U2 = makeU(l2), U3 = makeU(l3);
  int n1=2*l1+1, n2=2*l2+1, n3=2*l3+1;
  double tre[5][5][5] = {}, tim[5][5][5] = {};
  double mre=0.0, mim=0.0;
  for (int a=0;a<n1;++a) for (int b=0;b<n2;++b) for (int c=0;c<n3;++c){
    CD acc{0.0,0.0};
    for (int m=0;m<n1;++m) for (int n=0;n<n2;++n){
      int o = (m-l1)+(n-l2)+l3;
      if (o < 0 || o >= n3) continue;
      double cg = cgc(l1,l2,l3, m-l1, n-l2);
      if (cg == 0.0) continue;
      CD t = cmulc(cmulc(U1.u[a][m], U2.u[b][n]), conjc(U3.u[c][o]));
      acc.re += t.re*cg; acc.im += t.im*cg;
    }
    tre[a][b][c]=acc.re; tim[a][b][c]=acc.im;
    double ar = acc.re<0.0?-acc.re:acc.re;
    double ai = acc.im<0.0?-acc.im:acc.im;
    if (ar>mre) mre=ar;
    if (ai>mim) mim=ai;
  }
  CG3 R{};
  for (int a=0;a<n1;++a) for (int b=0;b<n2;++b) for (int c=0;c<n3;++c){
    double vv = (mre >= mim) ? tre[a][b][c] : tim[a][b][c];
    if (vv < 1e-12 && vv > -1e-12) vv = 0.0;
    R.v[a][b][c] = vv;
  }
  return R;
}

__device__ __forceinline__ float silu(float x){
  return __fdividef(x, 1.0f + __expf(-x));
}

// ============================================================
// mma.sync m16n8k16 bf16 (standard PTX, legal on base sm_103 target)
// ============================================================
__device__ __forceinline__ void mma16816(float d[4], const uint32_t a[4], const uint32_t b[2]){
  asm volatile("mma.sync.aligned.m16n8k16.row.col.f32.bf16.bf16.f32 "
    "{%0,%1,%2,%3}, {%4,%5,%6,%7}, {%8,%9}, {%0,%1,%2,%3};"
    : "+f"(d[0]), "+f"(d[1]), "+f"(d[2]), "+f"(d[3])
    : "r"(a[0]), "r"(a[1]), "r"(a[2]), "r"(a[3]), "r"(b[0]), "r"(b[1]));
}

// split a pair of f32 into packed bf16 hi word + bf16 residual word
__device__ __forceinline__ void split2(float y0, float y1, uint32_t& hi, uint32_t& lo){
  __nv_bfloat16 h0 = __float2bfloat16(y0), h1 = __float2bfloat16(y1);
  float r0 = y0 - __bfloat162float(h0);
  float r1 = y1 - __bfloat162float(h1);
  hi = ((uint32_t)__bfloat16_as_ushort(h1) << 16) | (uint32_t)__bfloat16_as_ushort(h0);
  __nv_bfloat16 l0 = __float2bfloat16(r0), l1 = __float2bfloat16(r1);
  lo = ((uint32_t)__bfloat16_as_ushort(l1) << 16) | (uint32_t)__bfloat16_as_ushort(l0);
}

// ============================================================
// SMEM layout (bytes). Weights as [n][k] bf16, row strides chosen so that
// every 8-row x 4-consecutive-word fragment load partitions the 32 banks:
// stride(words) mod 32 must generate {0..31} over (8 rows x 4 words).
//   K=16 rows: stride 12 words (48 B)   K=64 rows: stride 36 words (144 B)
// ============================================================
#define SM_W0H 0          // 64 * 48
#define SM_W0L 3072
#define SM_W1H 6144       // 64 * 144
#define SM_W1L 15360
#define SM_W2H 24576      // 288 * 144
#define SM_W2L 66048
#define SM_XH  107520     // 256 * 48
#define SM_XL  119808
#define SM_TOT 132096

__global__ __launch_bounds__(256)
void mlp_mma_kernel(const float* __restrict__ ef,
                    const float* __restrict__ W0,
                    const float* __restrict__ W1,
                    const float* __restrict__ W2,
                    int E){
  extern __shared__ char sm[];
  int t = threadIdx.x;
  int lane = t & 31, wid = t >> 5;
  int grp = lane >> 2, qt = lane & 3;
  int m0 = wid * 32;

  // ---- stage weights hi/lo, once per persistent block ----
  for (int idx = t; idx < 16*64; idx += 256){
    int k = idx >> 6, n = idx & 63;
    float v = W0[idx];
    __nv_bfloat16 h = __float2bfloat16(v);
    float r = v - __bfloat162float(h);
    *(__nv_bfloat16*)(sm + SM_W0H + n*48 + k*2) = h;
    *(__nv_bfloat16*)(sm + SM_W0L + n*48 + k*2) = __float2bfloat16(r);
  }
  for (int idx = t; idx < 64*64; idx += 256){
    int k = idx >> 6, n = idx & 63;
    float v = W1[idx];
    __nv_bfloat16 h = __float2bfloat16(v);
    float r = v - __bfloat162float(h);
    *(__nv_bfloat16*)(sm + SM_W1H + n*144 + k*2) = h;
    *(__nv_bfloat16*)(sm + SM_W1L + n*144 + k*2) = __float2bfloat16(r);
  }
  for (int idx = t; idx < 64*288; idx += 256){
    int k = idx / 288, n = idx % 288;
    float v = W2[idx];
    __nv_bfloat16 h = __float2bfloat16(v);
    float r = v - __bfloat162float(h);
    *(__nv_bfloat16*)(sm + SM_W2H + n*144 + k*2) = h;
    *(__nv_bfloat16*)(sm + SM_W2L + n*144 + k*2) = __float2bfloat16(r);
  }

  const uint32_t* XH  = (const uint32_t*)(sm + SM_XH);
  const uint32_t* XL  = (const uint32_t*)(sm + SM_XL);
  const uint32_t* W0H = (const uint32_t*)(sm + SM_W0H);
  const uint32_t* W0L = (const uint32_t*)(sm + SM_W0L);
  const uint32_t* W1H = (const uint32_t*)(sm + SM_W1H);
  const uint32_t* W1L = (const uint32_t*)(sm + SM_W1L);
  const uint32_t* W2H = (const uint32_t*)(sm + SM_W2H);
  const uint32_t* W2L = (const uint32_t*)(sm + SM_W2L);

  int ntiles = (E + 255) >> 8;
  for (int tile = blockIdx.x; tile < ntiles; tile += gridDim.x){
    __syncthreads();   // previous iteration's X readers done
    // ---- stage x (256 edges x 16) as bf16 hi/lo, row stride 12 words ----
    {
      int e = tile*256 + t;
      int ec = (e < E) ? e : (E - 1);
      const float4* src = (const float4*)(ef + (size_t)ec * NRBF);
      float4 v0 = src[0], v1 = src[1], v2 = src[2], v3 = src[3];
      float x[16] = { v0.x,v0.y,v0.z,v0.w, v1.x,v1.y,v1.z,v1.w,
                      v2.x,v2.y,v2.z,v2.w, v3.x,v3.y,v3.z,v3.w };
      uint32_t* xh = (uint32_t*)(sm + SM_XH) + t*12;
      uint32_t* xl = (uint32_t*)(sm + SM_XL) + t*12;
      #pragma unroll
      for (int c = 0; c < 8; ++c){
        uint32_t hi, lo;
        split2(x[2*c], x[2*c+1], hi, lo);
        xh[c] = hi; xl[c] = lo;
      }
    }
    __syncthreads();

    // ---- A1 fragments from X ----
    uint32_t a1h[2][4], a1l[2][4];
    #pragma unroll
    for (int mt = 0; mt < 2; ++mt){
      int r = m0 + mt*16 + grp;
      a1h[mt][0] = XH[r*12 + qt];      a1h[mt][1] = XH[(r+8)*12 + qt];
      a1h[mt][2] = XH[r*12 + qt + 4];  a1h[mt][3] = XH[(r+8)*12 + qt + 4];
      a1l[mt][0] = XL[r*12 + qt];      a1l[mt][1] = XL[(r+8)*12 + qt];
      a1l[mt][2] = XL[r*12 + qt + 4];  a1l[mt][3] = XL[(r+8)*12 + qt + 4];
    }

    // ---- Layer 1: X[32x16] @ W0 -> 64, split-3, D->A chain in regs ----
    uint32_t a2h[2][4][4], a2l[2][4][4];
    #pragma unroll
    for (int g = 0; g < 2; ++g){
      float acc[2][4][4];
      #pragma unroll
      for (int mt=0;mt<2;++mt)
        #pragma unroll
        for (int j=0;j<4;++j)
          #pragma unroll
          for (int q=0;q<4;++q) acc[mt][j][q] = 0.f;
      uint32_t bh[4][2], bl[4][2];
      #pragma unroll
      for (int j=0;j<4;++j){
        int rn = (g*4+j)*8 + grp;
        bh[j][0] = W0H[rn*12 + qt];  bh[j][1] = W0H[rn*12 + qt + 4];
        bl[j][0] = W0L[rn*12 + qt];  bl[j][1] = W0L[rn*12 + qt + 4];
      }
      #pragma unroll
      for (int mt=0;mt<2;++mt)
        #pragma unroll
        for (int j=0;j<4;++j) mma16816(acc[mt][j], a1h[mt], bh[j]);
      #pragma unroll
      for (int mt=0;mt<2;++mt)
        #pragma unroll
        for (int j=0;j<4;++j) mma16816(acc[mt][j], a1l[mt], bh[j]);
      #pragma unroll
      for (int mt=0;mt<2;++mt)
        #pragma unroll
        for (int j=0;j<4;++j) mma16816(acc[mt][j], a1h[mt], bl[j]);
      // epilogue: silu + split into A2 fragments (D layout == A layout)
      #pragma unroll
      for (int mt=0;mt<2;++mt)
        #pragma unroll
        for (int j=0;j<4;++j){
          int nt = g*4 + j, ks = nt >> 1, ix = (nt & 1) * 2;
          float y0 = silu(acc[mt][j][0]), y1 = silu(acc[mt][j][1]);
          float y2 = silu(acc[mt][j][2]), y3 = silu(acc[mt][j][3]);
          split2(y0, y1, a2h[mt][ks][ix],   a2l[mt][ks][ix]);
          split2(y2, y3, a2h[mt][ks][ix+1], a2l[mt][ks][ix+1]);
        }
    }

    // ---- Layer 2: 64 -> 64, K=64 (4 ksteps), split-3 ----
    uint32_t a3h[2][4][4], a3l[2][4][4];
    #pragma unroll
    for (int g = 0; g < 2; ++g){
      float acc[2][4][4];
      #pragma unroll
      for (int mt=0;mt<2;++mt)
        #pragma unroll
        for (int j=0;j<4;++j)
          #pragma unroll
          for (int q=0;q<4;++q) acc[mt][j][q] = 0.f;
      #pragma unroll
      for (int ks = 0; ks < 4; ++ks){
        uint32_t bh[4][2], bl[4][2];
        #pragma unroll
        for (int j=0;j<4;++j){
          int rn = (g*4+j)*8 + grp;
          int w = ks*8 + qt;
          bh[j][0] = W1H[rn*36 + w];  bh[j][1] = W1H[rn*36 + w + 4];
          bl[j][0] = W1L[rn*36 + w];  bl[j][1] = W1L[rn*36 + w + 4];
        }
        #pragma unroll
        for (int mt=0;mt<2;++mt)
          #pragma unroll
          for (int j=0;j<4;++j) mma16816(acc[mt][j], a2h[mt][ks], bh[j]);
        #pragma unroll
        for (int mt=0;mt<2;++mt)
          #pragma unroll
          for (int j=0;j<4;++j) mma16816(acc[mt][j], a2l[mt][ks], bh[j]);
        #pragma unroll
        for (int mt=0;mt<2;++mt)
          #pragma unroll
          for (int j=0;j<4;++j) mma16816(acc[mt][j], a2h[mt][ks], bl[j]);
      }
      #pragma unroll
      for (int mt=0;mt<2;++mt)
        #pragma unroll
        for (int j=0;j<4;++j){
          int nt = g*4 + j, ks = nt >> 1, ix = (nt & 1) * 2;
          float y0 = silu(acc[mt][j][0]), y1 = silu(acc[mt][j][1]);
          float y2 = silu(acc[mt][j][2]), y3 = silu(acc[mt][j][3]);
          split2(y0, y1, a3h[mt][ks][ix],   a3l[mt][ks][ix]);
          split2(y2, y3, a3h[mt][ks][ix+1], a3l[mt][ks][ix+1]);
        }
    }

    // ---- Layer 3: 64 -> 288 (36 n-tiles, 12 groups of 3), split-3 ----
    #pragma unroll 1
    for (int g = 0; g < 12; ++g){
      float acc[2][3][4];
      #pragma unroll
      for (int mt=0;mt<2;++mt)
        #pragma unroll
        for (int j=0;j<3;++j)
          #pragma unroll
          for (int q=0;q<4;++q) acc[mt][j][q] = 0.f;
      #pragma unroll
      for (int ks = 0; ks < 4; ++ks){
        uint32_t bh[3][2], bl[3][2];
        #pragma unroll
        for (int j=0;j<3;++j){
          int rn = (g*3+j)*8 + grp;
          int w = ks*8 + qt;
          bh[j][0] = W2H[rn*36 + w];  bh[j][1] = W2H[rn*36 + w + 4];
          bl[j][0] = W2L[rn*36 + w];  bl[j][1] = W2L[rn*36 + w + 4];
        }
        #pragma unroll
        for (int mt=0;mt<2;++mt)
          #pragma unroll
          for (int j=0;j<3;++j) mma16816(acc[mt][j], a3h[mt][ks], bh[j]);
        #pragma unroll
        for (int mt=0;mt<2;++mt)
          #pragma unroll
          for (int j=0;j<3;++j) mma16816(acc[mt][j], a3l[mt][ks], bh[j]);
        #pragma unroll
        for (int mt=0;mt<2;++mt)
          #pragma unroll
          for (int j=0;j<3;++j) mma16816(acc[mt][j], a3h[mt][ks], bl[j]);
      }
      // epilogue: silu + f32 store to g_w
      #pragma unroll
      for (int mt=0;mt<2;++mt)
        #pragma unroll
        for (int j=0;j<3;++j){
          int e0 = tile*256 + m0 + mt*16 + grp;
          int col = (g*3+j)*8 + 2*qt;
          if (e0 < E){
            float2 v = make_float2(silu(acc[mt][j][0]), silu(acc[mt][j][1]));
            *(float2*)(g_w + (size_t)e0*NW + col) = v;
          }
          if (e0 + 8 < E){
            float2 v = make_float2(silu(acc[mt][j][2]), silu(acc[mt][j][3]));
            *(float2*)(g_w + (size_t)(e0+8)*NW + col) = v;
          }
        }
    }
  }
}

// ============================================================
// Kernel B: tensor product + smem-staged coalesced scatter-add.
// ============================================================
template<int L1, int L2, int L3>
__device__ __forceinline__ void do_path(float wp, const float* x, const float* Y, float* o){
  constexpr CG3 cg = make_cg(L1, L2, L3);
  #pragma unroll
  for (int a = 0; a < 2*L1+1; ++a){
    float wx = wp * x[a];
    #pragma unroll
    for (int b = 0; b < 2*L2+1; ++b){
      #pragma unroll
      for (int c = 0; c < 2*L3+1; ++c){
        const float v = (float)cg.v[a][b][c];
        if (v != 0.0f){
          o[c] += wx * (v * Y[b]);
        }
      }
    }
  }
}

__global__ __launch_bounds__(256)
void tp_kernel(const float* __restrict__ nf,
               const float* __restrict__ evec,
               const int*   __restrict__ eidx,
               float* __restrict__ out,
               int E){
  __shared__ float sb[8][NW];
  int warp = (blockIdx.x * blockDim.x + threadIdx.x) >> 5;
  int wi = (threadIdx.x >> 5);
  int lane = threadIdx.x & 31;
  if (warp >= E) return;
  int e = warp;

  int src = eidx[2*e+0];
  int dst = eidx[2*e+1];

  float vx = evec[3*e+0], vy = evec[3*e+1], vz = evec[3*e+2];
  float nrm = sqrtf(vx*vx + vy*vy + vz*vz);
  float inv = 1.0f / (nrm + 1e-12f);
  float X = vx*inv, Yv = vy*inv, Z = vz*inv;

  const float S3 = 1.7320508075688772f;
  float Y0[1] = {1.0f};
  float Y1[3] = {Yv, Z, X};
  float Y2[5] = {S3*X*Yv, S3*Yv*Z, 0.5f*(3.0f*Z*Z - 1.0f), S3*X*Z, 0.5f*S3*(X*X - Yv*Yv)};

  const float* nfr = nf + (size_t)src * (4*CMUL);
  float x0[1] = { nfr[lane] };
  float x1[3] = { nfr[CMUL + 3*lane + 0],
                  nfr[CMUL + 3*lane + 1],
                  nfr[CMUL + 3*lane + 2] };

  const float* wr = g_w + (size_t)e * NW;
  float o0[1] = {0.f};
  float o1[3] = {0.f,0.f,0.f};
  float o2[5] = {0.f,0.f,0.f,0.f,0.f};

  do_path<0,0,0>(wr[0*CMUL + lane], x0, Y0, o0);
  do_path<0,1,1>(wr[1*CMUL + lane], x0, Y1, o1);
  do_path<0,2,2>(wr[2*CMUL + lane], x0, Y2, o2);
  do_path<1,0,1>(wr[3*CMUL + lane], x1, Y0, o1);
  do_path<1,1,0>(wr[4*CMUL + lane], x1, Y1, o0);
  do_path<1,1,1>(wr[5*CMUL + lane], x1, Y1, o1);
  do_path<1,1,2>(wr[6*CMUL + lane], x1, Y1, o2);
  do_path<1,2,1>(wr[7*CMUL + lane], x1, Y2, o1);
  do_path<1,2,2>(wr[8*CMUL + lane], x1, Y2, o2);

  sb[wi][lane] = o0[0];
  #pragma unroll
  for (int c = 0; c < 3; ++c) sb[wi][CMUL + 3*lane + c] = o1[c];
  #pragma unroll
  for (int c = 0; c < 5; ++c) sb[wi][4*CMUL + 5*lane + c] = o2[c];
  __syncwarp();

  float* orow = out + (size_t)dst * NW;
  #pragma unroll
  for (int p = 0; p < 9; ++p)
    atomicAdd(orow + p*32 + lane, sb[wi][p*32 + lane]);
}

// ============================================================
// Launch
// ============================================================
extern "C" void kernel_launch(void* const* d_in, const int* in_sizes, int n_in,
                              void* d_out, int out_size){
  const float* nf = (const float*)d_in[0];
  const float* ef = (const float*)d_in[1];
  const float* ev = (const float*)d_in[2];
  const int*   ei = (const int*)  d_in[3];
  const float* W0 = (const float*)d_in[4];
  const float* W1 = (const float*)d_in[5];
  const float* W2 = (const float*)d_in[6];
  float* out = (float*)d_out;

  int E = in_sizes[2] / 3;
  if (E > MAX_E) E = MAX_E;

  cudaMemsetAsync(d_out, 0, (size_t)out_size * sizeof(float), 0);

  cudaFuncSetAttribute(mlp_mma_kernel, cudaFuncAttributeMaxDynamicSharedMemorySize, SM_TOT);
  mlp_mma_kernel<<<148, 256, SM_TOT>>>(ef, W0, W1, W2, E);

  int blocksB = (E * 32 + 255) / 256;
  tp_kernel<<<blocksB, 256>>>(nf, ev, ei, out, E);
}

// round 8
// speedup vs baseline: 3.1400x; 1.2102x over previous
#include <cuda_runtime.h>
#include <cuda_bf16.h>
#include <cstdint>
#include <cstddef>

// ============================================================
// Problem constants
// ============================================================
#define MAX_E   320000
#define NRBF    16
#define DH      64
#define NW      288
#define CMUL    32

// scratch for per-edge MLP outputs w (E x 288), fp32
__device__ float g_w[(size_t)MAX_E * NW];

// ============================================================
// Compile-time Clebsch-Gordan (exact port of the reference math)
// ============================================================
struct CD { double re, im; };
__host__ __device__ constexpr CD cmulc(CD a, CD b){ return CD{a.re*b.re - a.im*b.im, a.re*b.im + a.im*b.re}; }
__host__ __device__ constexpr CD conjc(CD a){ return CD{a.re, -a.im}; }
__host__ __device__ constexpr double cfact(int n){ double r=1.0; for(int i=2;i<=n;++i) r*= (double)i; return r; }
__host__ __device__ constexpr double csqrt(double x){
  if (x <= 0.0) return 0.0;
  double r = x < 1.0 ? 1.0 : x;
  for (int i=0;i<200;++i) r = 0.5*(r + x/r);
  return r;
}
__host__ __device__ constexpr double cgc(int l1,int l2,int l3,int m1,int m2){
  int m3 = m1+m2;
  if (m3 < -l3 || m3 > l3) return 0.0;
  double pref = csqrt((double)(2*l3+1)*cfact(l1+l2-l3)*cfact(l1-l2+l3)*cfact(-l1+l2+l3)/cfact(l1+l2+l3+1));
  pref *= csqrt(cfact(l3+m3)*cfact(l3-m3)*cfact(l1-m1)*cfact(l1+m1)*cfact(l2-m2)*cfact(l2+m2));
  double s = 0.0;
  for (int k=0;k<=l1+l2-l3;++k){
    int a1=l1+l2-l3-k, a2=l1-m1-k, a3=l2+m2-k, a4=l3-l2+m1+k, a5=l3-l1-m2+k;
    if (a1<0||a2<0||a3<0||a4<0||a5<0) continue;
    double d = cfact(k)*cfact(a1)*cfact(a2)*cfact(a3)*cfact(a4)*cfact(a5);
    s += ((k&1)? -1.0 : 1.0)/d;
  }
  return pref*s;
}
struct UMat { CD u[5][5]; };
__host__ __device__ constexpr UMat makeU(int l){
  UMat U{};
  const double s = 1.0/csqrt(2.0);
  U.u[l][l] = CD{1.0, 0.0};
  for (int m=1;m<=l;++m){
    double sg = (m&1)? -1.0 : 1.0;
    U.u[l+m][l+m] = CD{sg*s, 0.0};
    U.u[l+m][l-m] = CD{s, 0.0};
    U.u[l-m][l-m] = CD{0.0, s};
    U.u[l-m][l+m] = CD{0.0, -sg*s};
  }
  return U;
}
struct CG3 { double v[5][5][5]; };
__host__ __device__ constexpr CG3 make_cg(int l1,int l2,int l3){
  UMat U1 = makeU(l1), U2 = makeU(l2), U3 = makeU(l3);
  int n1=2*l1+1, n2=2*l2+1, n3=2*l3+1;
  double tre[5][5][5] = {}, tim[5][5][5] = {};
  double mre=0.0, mim=0.0;
  for (int a=0;a<n1;++a) for (int b=0;b<n2;++b) for (int c=0;c<n3;++c){
    CD acc{0.0,0.0};
    for (int m=0;m<n1;++m) for (int n=0;n<n2;++n){
      int o = (m-l1)+(n-l2)+l3;
      if (o < 0 || o >= n3) continue;
      double cg = cgc(l1,l2,l3, m-l1, n-l2);
      if (cg == 0.0) continue;
      CD t = cmulc(cmulc(U1.u[a][m], U2.u[b][n]), conjc(U3.u[c][o]));
      acc.re += t.re*cg; acc.im += t.im*cg;
    }
    tre[a][b][c]=acc.re; tim[a][b][c]=acc.im;
    double ar = acc.re<0.0?-acc.re:acc.re;
    double ai = acc.im<0.0?-acc.im:acc.im;
    if (ar>mre) mre=ar;
    if (ai>mim) mim=ai;
  }
  CG3 R{};
  for (int a=0;a<n1;++a) for (int b=0;b<n2;++b) for (int c=0;c<n3;++c){
    double vv = (mre >= mim) ? tre[a][b][c] : tim[a][b][c];
    if (vv < 1e-12 && vv > -1e-12) vv = 0.0;
    R.v[a][b][c] = vv;
  }
  return R;
}

// exp-based silu (used where errors propagate through layers)
__device__ __forceinline__ float silu(float x){
  return __fdividef(x, 1.0f + __expf(-x));
}
// tanh-based silu: 1 MUFU. silu(x) = h + h*tanh(h), h = x/2.
__device__ __forceinline__ float silu_t(float x){
  float h = 0.5f * x;
  float t;
  asm("tanh.approx.f32 %0, %1;" : "=f"(t) : "f"(h));
  return fmaf(h, t, h);
}

// ============================================================
// mma.sync m16n8k16 bf16 (standard PTX, legal on base sm_103 target)
// ============================================================
__device__ __forceinline__ void mma16816(float d[4], const uint32_t a[4], const uint32_t b[2]){
  asm volatile("mma.sync.aligned.m16n8k16.row.col.f32.bf16.bf16.f32 "
    "{%0,%1,%2,%3}, {%4,%5,%6,%7}, {%8,%9}, {%0,%1,%2,%3};"
    : "+f"(d[0]), "+f"(d[1]), "+f"(d[2]), "+f"(d[3])
    : "r"(a[0]), "r"(a[1]), "r"(a[2]), "r"(a[3]), "r"(b[0]), "r"(b[1]));
}

// split a pair of f32 into packed bf16 hi word + bf16 residual word
__device__ __forceinline__ void split2(float y0, float y1, uint32_t& hi, uint32_t& lo){
  uint32_t h;
  asm("cvt.rn.bf16x2.f32 %0, %1, %2;" : "=r"(h) : "f"(y1), "f"(y0));
  float f0 = __uint_as_float(h << 16);
  float f1 = __uint_as_float(h & 0xffff0000u);
  float r0 = y0 - f0;
  float r1 = y1 - f1;
  uint32_t l;
  asm("cvt.rn.bf16x2.f32 %0, %1, %2;" : "=r"(l) : "f"(r1), "f"(r0));
  hi = h; lo = l;
}

// ============================================================
// SMEM layout (bytes). Weights as [n][k] bf16, row strides chosen so that
// every 8-row x 4-consecutive-word fragment load partitions the 32 banks:
//   K=16 rows: stride 12 words (48 B)   K=64 rows: stride 36 words (144 B)
// ============================================================
#define SM_W0H 0          // 64 * 48
#define SM_W0L 3072
#define SM_W1H 6144       // 64 * 144
#define SM_W1L 15360
#define SM_W2H 24576      // 288 * 144
#define SM_W2L 66048
#define SM_XH  107520     // 256 * 48
#define SM_XL  119808
#define SM_TOT 132096

#define MLP_THREADS 512   // 16 warps x 16 edges = 256-edge tiles

__global__ __launch_bounds__(MLP_THREADS)
void mlp_mma_kernel(const float* __restrict__ ef,
                    const float* __restrict__ W0,
                    const float* __restrict__ W1,
                    const float* __restrict__ W2,
                    int E){
  extern __shared__ char sm[];
  int t = threadIdx.x;
  int lane = t & 31, wid = t >> 5;
  int grp = lane >> 2, qt = lane & 3;
  int m0 = wid * 16;          // 16 edges per warp

  // ---- stage weights hi/lo, once per persistent block ----
  for (int idx = t; idx < 16*64; idx += MLP_THREADS){
    int k = idx >> 6, n = idx & 63;
    float v = W0[idx];
    __nv_bfloat16 h = __float2bfloat16(v);
    float r = v - __bfloat162float(h);
    *(__nv_bfloat16*)(sm + SM_W0H + n*48 + k*2) = h;
    *(__nv_bfloat16*)(sm + SM_W0L + n*48 + k*2) = __float2bfloat16(r);
  }
  for (int idx = t; idx < 64*64; idx += MLP_THREADS){
    int k = idx >> 6, n = idx & 63;
    float v = W1[idx];
    __nv_bfloat16 h = __float2bfloat16(v);
    float r = v - __bfloat162float(h);
    *(__nv_bfloat16*)(sm + SM_W1H + n*144 + k*2) = h;
    *(__nv_bfloat16*)(sm + SM_W1L + n*144 + k*2) = __float2bfloat16(r);
  }
  for (int idx = t; idx < 64*288; idx += MLP_THREADS){
    int k = idx / 288, n = idx % 288;
    float v = W2[idx];
    __nv_bfloat16 h = __float2bfloat16(v);
    float r = v - __bfloat162float(h);
    *(__nv_bfloat16*)(sm + SM_W2H + n*144 + k*2) = h;
    *(__nv_bfloat16*)(sm + SM_W2L + n*144 + k*2) = __float2bfloat16(r);
  }

  const uint32_t* XH  = (const uint32_t*)(sm + SM_XH);
  const uint32_t* XL  = (const uint32_t*)(sm + SM_XL);
  const uint32_t* W0H = (const uint32_t*)(sm + SM_W0H);
  const uint32_t* W0L = (const uint32_t*)(sm + SM_W0L);
  const uint32_t* W1H = (const uint32_t*)(sm + SM_W1H);
  const uint32_t* W1L = (const uint32_t*)(sm + SM_W1L);
  const uint32_t* W2H = (const uint32_t*)(sm + SM_W2H);
  const uint32_t* W2L = (const uint32_t*)(sm + SM_W2L);

  int ntiles = (E + 255) >> 8;
  for (int tile = blockIdx.x; tile < ntiles; tile += gridDim.x){
    __syncthreads();   // previous iteration's X readers done
    // ---- stage x (256 edges x 16) as bf16 hi/lo, row stride 12 words ----
    if (t < 256){
      int e = tile*256 + t;
      int ec = (e < E) ? e : (E - 1);
      const float4* src = (const float4*)(ef + (size_t)ec * NRBF);
      float4 v0 = src[0], v1 = src[1], v2 = src[2], v3 = src[3];
      float x[16] = { v0.x,v0.y,v0.z,v0.w, v1.x,v1.y,v1.z,v1.w,
                      v2.x,v2.y,v2.z,v2.w, v3.x,v3.y,v3.z,v3.w };
      uint32_t* xh = (uint32_t*)(sm + SM_XH) + t*12;
      uint32_t* xl = (uint32_t*)(sm + SM_XL) + t*12;
      #pragma unroll
      for (int c = 0; c < 8; ++c){
        uint32_t hi, lo;
        split2(x[2*c], x[2*c+1], hi, lo);
        xh[c] = hi; xl[c] = lo;
      }
    }
    __syncthreads();

    // ---- A1 fragments from X (16 rows: grp, grp+8) ----
    uint32_t a1h[4], a1l[4];
    {
      int r = m0 + grp;
      a1h[0] = XH[r*12 + qt];      a1h[1] = XH[(r+8)*12 + qt];
      a1h[2] = XH[r*12 + qt + 4];  a1h[3] = XH[(r+8)*12 + qt + 4];
      a1l[0] = XL[r*12 + qt];      a1l[1] = XL[(r+8)*12 + qt];
      a1l[2] = XL[r*12 + qt + 4];  a1l[3] = XL[(r+8)*12 + qt + 4];
    }

    // ---- Layer 1: 16 -> 64, split-3, D->A chain in regs ----
    uint32_t a2h[4][4], a2l[4][4];
    #pragma unroll
    for (int g = 0; g < 2; ++g){
      float acc[4][4];
      #pragma unroll
      for (int j=0;j<4;++j)
        #pragma unroll
        for (int q=0;q<4;++q) acc[j][q] = 0.f;
      uint32_t bh[4][2], bl[4][2];
      #pragma unroll
      for (int j=0;j<4;++j){
        int rn = (g*4+j)*8 + grp;
        bh[j][0] = W0H[rn*12 + qt];  bh[j][1] = W0H[rn*12 + qt + 4];
        bl[j][0] = W0L[rn*12 + qt];  bl[j][1] = W0L[rn*12 + qt + 4];
      }
      #pragma unroll
      for (int j=0;j<4;++j) mma16816(acc[j], a1h, bh[j]);
      #pragma unroll
      for (int j=0;j<4;++j) mma16816(acc[j], a1l, bh[j]);
      #pragma unroll
      for (int j=0;j<4;++j) mma16816(acc[j], a1h, bl[j]);
      #pragma unroll
      for (int j=0;j<4;++j){
        int nt = g*4 + j, ks = nt >> 1, ix = (nt & 1) * 2;
        float y0 = silu(acc[j][0]), y1 = silu(acc[j][1]);
        float y2 = silu(acc[j][2]), y3 = silu(acc[j][3]);
        split2(y0, y1, a2h[ks][ix],   a2l[ks][ix]);
        split2(y2, y3, a2h[ks][ix+1], a2l[ks][ix+1]);
      }
    }

    // ---- Layer 2: 64 -> 64, K=64 (4 ksteps), split-3 ----
    uint32_t a3h[4][4], a3l[4][4];
    #pragma unroll
    for (int g = 0; g < 2; ++g){
      float acc[4][4];
      #pragma unroll
      for (int j=0;j<4;++j)
        #pragma unroll
        for (int q=0;q<4;++q) acc[j][q] = 0.f;
      #pragma unroll
      for (int ks = 0; ks < 4; ++ks){
        uint32_t bh[4][2], bl[4][2];
        #pragma unroll
        for (int j=0;j<4;++j){
          int rn = (g*4+j)*8 + grp;
          int w = ks*8 + qt;
          bh[j][0] = W1H[rn*36 + w];  bh[j][1] = W1H[rn*36 + w + 4];
          bl[j][0] = W1L[rn*36 + w];  bl[j][1] = W1L[rn*36 + w + 4];
        }
        #pragma unroll
        for (int j=0;j<4;++j) mma16816(acc[j], a2h[ks], bh[j]);
        #pragma unroll
        for (int j=0;j<4;++j) mma16816(acc[j], a2l[ks], bh[j]);
        #pragma unroll
        for (int j=0;j<4;++j) mma16816(acc[j], a2h[ks], bl[j]);
      }
      #pragma unroll
      for (int j=0;j<4;++j){
        int nt = g*4 + j, ks = nt >> 1, ix = (nt & 1) * 2;
        float y0 = silu(acc[j][0]), y1 = silu(acc[j][1]);
        float y2 = silu(acc[j][2]), y3 = silu(acc[j][3]);
        split2(y0, y1, a3h[ks][ix],   a3l[ks][ix]);
        split2(y2, y3, a3h[ks][ix+1], a3l[ks][ix+1]);
      }
    }

    // ---- Layer 3: 64 -> 288 (36 n-tiles, 12 groups of 3), split-3 ----
    #pragma unroll 1
    for (int g = 0; g < 12; ++g){
      float acc[3][4];
      #pragma unroll
      for (int j=0;j<3;++j)
        #pragma unroll
        for (int q=0;q<4;++q) acc[j][q] = 0.f;
      #pragma unroll
      for (int ks = 0; ks < 4; ++ks){
        uint32_t bh[3][2], bl[3][2];
        #pragma unroll
        for (int j=0;j<3;++j){
          int rn = (g*3+j)*8 + grp;
          int w = ks*8 + qt;
          bh[j][0] = W2H[rn*36 + w];  bh[j][1] = W2H[rn*36 + w + 4];
          bl[j][0] = W2L[rn*36 + w];  bl[j][1] = W2L[rn*36 + w + 4];
        }
        #pragma unroll
        for (int j=0;j<3;++j) mma16816(acc[j], a3h[ks], bh[j]);
        #pragma unroll
        for (int j=0;j<3;++j) mma16816(acc[j], a3l[ks], bh[j]);
        #pragma unroll
        for (int j=0;j<3;++j) mma16816(acc[j], a3h[ks], bl[j]);
      }
      // epilogue: tanh-silu + f32 store to g_w
      #pragma unroll
      for (int j=0;j<3;++j){
        int e0 = tile*256 + m0 + grp;
        int col = (g*3+j)*8 + 2*qt;
        if (e0 < E){
          float2 v = make_float2(silu_t(acc[j][0]), silu_t(acc[j][1]));
          *(float2*)(g_w + (size_t)e0*NW + col) = v;
        }
        if (e0 + 8 < E){
          float2 v = make_float2(silu_t(acc[j][2]), silu_t(acc[j][3]));
          *(float2*)(g_w + (size_t)(e0+8)*NW + col) = v;
        }
      }
    }
  }
}

// ============================================================
// Kernel B: tensor product + smem-staged coalesced scatter-add.
// ============================================================
template<int L1, int L2, int L3>
__device__ __forceinline__ void do_path(float wp, const float* x, const float* Y, float* o){
  constexpr CG3 cg = make_cg(L1, L2, L3);
  #pragma unroll
  for (int a = 0; a < 2*L1+1; ++a){
    float wx = wp * x[a];
    #pragma unroll
    for (int b = 0; b < 2*L2+1; ++b){
      #pragma unroll
      for (int c = 0; c < 2*L3+1; ++c){
        const float v = (float)cg.v[a][b][c];
        if (v != 0.0f){
          o[c] += wx * (v * Y[b]);
        }
      }
    }
  }
}

__global__ __launch_bounds__(256)
void tp_kernel(const float* __restrict__ nf,
               const float* __restrict__ evec,
               const int*   __restrict__ eidx,
               float* __restrict__ out,
               int E){
  __shared__ float sb[8][NW];
  int warp = (blockIdx.x * blockDim.x + threadIdx.x) >> 5;
  int wi = (threadIdx.x >> 5);
  int lane = threadIdx.x & 31;
  if (warp >= E) return;
  int e = warp;

  int src = eidx[2*e+0];
  int dst = eidx[2*e+1];

  float vx = evec[3*e+0], vy = evec[3*e+1], vz = evec[3*e+2];
  float nrm = sqrtf(vx*vx + vy*vy + vz*vz);
  float inv = 1.0f / (nrm + 1e-12f);
  float X = vx*inv, Yv = vy*inv, Z = vz*inv;

  const float S3 = 1.7320508075688772f;
  float Y0[1] = {1.0f};
  float Y1[3] = {Yv, Z, X};
  float Y2[5] = {S3*X*Yv, S3*Yv*Z, 0.5f*(3.0f*Z*Z - 1.0f), S3*X*Z, 0.5f*S3*(X*X - Yv*Yv)};

  const float* nfr = nf + (size_t)src * (4*CMUL);
  float x0[1] = { nfr[lane] };
  float x1[3] = { nfr[CMUL + 3*lane + 0],
                  nfr[CMUL + 3*lane + 1],
                  nfr[CMUL + 3*lane + 2] };

  const float* wr = g_w + (size_t)e * NW;
  float o0[1] = {0.f};
  float o1[3] = {0.f,0.f,0.f};
  float o2[5] = {0.f,0.f,0.f,0.f,0.f};

  do_path<0,0,0>(wr[0*CMUL + lane], x0, Y0, o0);
  do_path<0,1,1>(wr[1*CMUL + lane], x0, Y1, o1);
  do_path<0,2,2>(wr[2*CMUL + lane], x0, Y2, o2);
  do_path<1,0,1>(wr[3*CMUL + lane], x1, Y0, o1);
  do_path<1,1,0>(wr[4*CMUL + lane], x1, Y1, o0);
  do_path<1,1,1>(wr[5*CMUL + lane], x1, Y1, o1);
  do_path<1,1,2>(wr[6*CMUL + lane], x1, Y1, o2);
  do_path<1,2,1>(wr[7*CMUL + lane], x1, Y2, o1);
  do_path<1,2,2>(wr[8*CMUL + lane], x1, Y2, o2);

  sb[wi][lane] = o0[0];
  #pragma unroll
  for (int c = 0; c < 3; ++c) sb[wi][CMUL + 3*lane + c] = o1[c];
  #pragma unroll
  for (int c = 0; c < 5; ++c) sb[wi][4*CMUL + 5*lane + c] = o2[c];
  __syncwarp();

  float* orow = out + (size_t)dst * NW;
  #pragma unroll
  for (int p = 0; p < 9; ++p)
    atomicAdd(orow + p*32 + lane, sb[wi][p*32 + lane]);
}

// ============================================================
// Launch
// ============================================================
extern "C" void kernel_launch(void* const* d_in, const int* in_sizes, int n_in,
                              void* d_out, int out_size){
  const float* nf = (const float*)d_in[0];
  const float* ef = (const float*)d_in[1];
  const float* ev = (const float*)d_in[2];
  const int*   ei = (const int*)  d_in[3];
  const float* W0 = (const float*)d_in[4];
  const float* W1 = (const float*)d_in[5];
  const float* W2 = (const float*)d_in[6];
  float* out = (float*)d_out;

  int E = in_sizes[2] / 3;
  if (E > MAX_E) E = MAX_E;

  cudaMemsetAsync(d_out, 0, (size_t)out_size * sizeof(float), 0);

  cudaFuncSetAttribute(mlp_mma_kernel, cudaFuncAttributeMaxDynamicSharedMemorySize, SM_TOT);
  mlp_mma_kernel<<<148, MLP_THREADS, SM_TOT>>>(ef, W0, W1, W2, E);

  int blocksB = (E * 32 + 255) / 256;
  tp_kernel<<<blocksB, 256>>>(nf, ev, ei, out, E);
}

// round 9
// speedup vs baseline: 3.6963x; 1.1772x over previous
#include <cuda_runtime.h>
#include <cuda_fp16.h>
#include <cstdint>
#include <cstddef>

// ============================================================
// Problem constants
// ============================================================
#define MAX_E   320000
#define NRBF    16
#define DH      64
#define NW      288
#define CMUL    32

// scratch for per-edge MLP outputs w (E x 288), fp16
__device__ __half g_w[(size_t)MAX_E * NW];

// ============================================================
// Compile-time Clebsch-Gordan (exact port of the reference math)
// ============================================================
struct CD { double re, im; };
__host__ __device__ constexpr CD cmulc(CD a, CD b){ return CD{a.re*b.re - a.im*b.im, a.re*b.im + a.im*b.re}; }
__host__ __device__ constexpr CD conjc(CD a){ return CD{a.re, -a.im}; }
__host__ __device__ constexpr double cfact(int n){ double r=1.0; for(int i=2;i<=n;++i) r*= (double)i; return r; }
__host__ __device__ constexpr double csqrt(double x){
  if (x <= 0.0) return 0.0;
  double r = x < 1.0 ? 1.0 : x;
  for (int i=0;i<200;++i) r = 0.5*(r + x/r);
  return r;
}
__host__ __device__ constexpr double cgc(int l1,int l2,int l3,int m1,int m2){
  int m3 = m1+m2;
  if (m3 < -l3 || m3 > l3) return 0.0;
  double pref = csqrt((double)(2*l3+1)*cfact(l1+l2-l3)*cfact(l1-l2+l3)*cfact(-l1+l2+l3)/cfact(l1+l2+l3+1));
  pref *= csqrt(cfact(l3+m3)*cfact(l3-m3)*cfact(l1-m1)*cfact(l1+m1)*cfact(l2-m2)*cfact(l2+m2));
  double s = 0.0;
  for (int k=0;k<=l1+l2-l3;++k){
    int a1=l1+l2-l3-k, a2=l1-m1-k, a3=l2+m2-k, a4=l3-l2+m1+k, a5=l3-l1-m2+k;
    if (a1<0||a2<0||a3<0||a4<0||a5<0) continue;
    double d = cfact(k)*cfact(a1)*cfact(a2)*cfact(a3)*cfact(a4)*cfact(a5);
    s += ((k&1)? -1.0 : 1.0)/d;
  }
  return pref*s;
}
struct UMat { CD u[5][5]; };
__host__ __device__ constexpr UMat makeU(int l){
  UMat U{};
  const double s = 1.0/csqrt(2.0);
  U.u[l][l] = CD{1.0, 0.0};
  for (int m=1;m<=l;++m){
    double sg = (m&1)? -1.0 : 1.0;
    U.u[l+m][l+m] = CD{sg*s, 0.0};
    U.u[l+m][l-m] = CD{s, 0.0};
    U.u[l-m][l-m] = CD{0.0, s};
    U.u[l-m][l+m] = CD{0.0, -sg*s};
  }
  return U;
}
struct CG3 { double v[5][5][5]; };
__host__ __device__ constexpr CG3 make_cg(int l1,int l2,int l3){
  UMat U1 = makeU(l1), U2 = makeU(l2), U3 = makeU(l3);
  int n1=2*l1+1, n2=2*l2+1, n3=2*l3+1;
  double tre[5][5][5] = {}, tim[5][5][5] = {};
  double mre=0.0, mim=0.0;
  for (int a=0;a<n1;++a) for (int b=0;b<n2;++b) for (int c=0;c<n3;++c){
    CD acc{0.0,0.0};
    for (int m=0;m<n1;++m) for (int n=0;n<n2;++n){
      int o = (m-l1)+(n-l2)+l3;
      if (o < 0 || o >= n3) continue;
      double cg = cgc(l1,l2,l3, m-l1, n-l2);
      if (cg == 0.0) continue;
      CD t = cmulc(cmulc(U1.u[a][m], U2.u[b][n]), conjc(U3.u[c][o]));
      acc.re += t.re*cg; acc.im += t.im*cg;
    }
    tre[a][b][c]=acc.re; tim[a][b][c]=acc.im;
    double ar = acc.re<0.0?-acc.re:acc.re;
    double ai = acc.im<0.0?-acc.im:acc.im;
    if (ar>mre) mre=ar;
    if (ai>mim) mim=ai;
  }
  CG3 R{};
  for (int a=0;a<n1;++a) for (int b=0;b<n2;++b) for (int c=0;c<n3;++c){
    double vv = (mre >= mim) ? tre[a][b][c] : tim[a][b][c];
    if (vv < 1e-12 && vv > -1e-12) vv = 0.0;
    R.v[a][b][c] = vv;
  }
  return R;
}

// tanh-based silu: 1 MUFU. silu(x) = h + h*tanh(h), h = x/2.
__device__ __forceinline__ float silu_t(float x){
  float h = 0.5f * x;
  float t;
  asm("tanh.approx.f32 %0, %1;" : "=f"(t) : "f"(h));
  return fmaf(h, t, h);
}

#define INV2048 4.8828125e-4f

// ============================================================
// mma.sync m16n8k16 fp16 (standard PTX, legal on base sm_103 target)
// ============================================================
__device__ __forceinline__ void mma16816(float d[4], const uint32_t a[4], const uint32_t b[2]){
  asm volatile("mma.sync.aligned.m16n8k16.row.col.f32.f16.f16.f32 "
    "{%0,%1,%2,%3}, {%4,%5,%6,%7}, {%8,%9}, {%0,%1,%2,%3};"
    : "+f"(d[0]), "+f"(d[1]), "+f"(d[2]), "+f"(d[3])
    : "r"(a[0]), "r"(a[1]), "r"(a[2]), "r"(a[3]), "r"(b[0]), "r"(b[1]));
}

__device__ __forceinline__ void ldm4(uint32_t addr, uint32_t* r){
  asm volatile("ldmatrix.sync.aligned.m8n8.x4.shared.b16 {%0,%1,%2,%3}, [%4];"
    : "=r"(r[0]), "=r"(r[1]), "=r"(r[2]), "=r"(r[3]) : "r"(addr));
}

// split into fp16 hi + fp16 residual scaled by 2048 (kept normal-range)
__device__ __forceinline__ void split2h(float y0, float y1, uint32_t& hi, uint32_t& lo){
  uint32_t h;
  asm("cvt.rn.f16x2.f32 %0, %1, %2;" : "=r"(h) : "f"(y1), "f"(y0));
  __half2 hh = *reinterpret_cast<__half2*>(&h);
  float2 hf = __half22float2(hh);
  float r0 = (y0 - hf.x) * 2048.0f;
  float r1 = (y1 - hf.y) * 2048.0f;
  uint32_t l;
  asm("cvt.rn.f16x2.f32 %0, %1, %2;" : "=r"(l) : "f"(r1), "f"(r0));
  hi = h; lo = l;
}

// ============================================================
// SMEM layout (bytes). fp16 weights [n][k], padded row strides so every
// ldmatrix 8-row x 16B read partitions the 32 banks:
//   K=16: stride 48B (12 words)    K=64: stride 144B (36 words)
// ============================================================
#define SM_W0  0          // 64 * 48   = 3072
#define SM_W1  3072       // 64 * 144  = 9216
#define SM_W2  12288      // 288 * 144 = 41472
#define SM_XH  53760      // 256 * 48  = 12288
#define SM_XL  66048      // 256 * 48
#define SM_TOT 78336

#define MLP_THREADS 512   // 16 warps x 16 edges = 256-edge tiles

__global__ __launch_bounds__(MLP_THREADS)
void mlp_mma_kernel(const float* __restrict__ ef,
                    const float* __restrict__ W0,
                    const float* __restrict__ W1,
                    const float* __restrict__ W2,
                    int E){
  extern __shared__ char sm[];
  uint32_t sm32 = (uint32_t)__cvta_generic_to_shared(sm);
  int t = threadIdx.x;
  int lane = t & 31, wid = t >> 5;
  int grp = lane >> 2, qt = lane & 3;
  int m0 = wid * 16;          // 16 edges per warp

  // per-lane ldmatrix offsets
  const uint32_t offA48  = ((uint32_t)(((lane>>3)&1)*8 + (lane&7)))*48 + (uint32_t)(lane>>4)*16;
  const uint32_t offB48  = (uint32_t)(lane>>4)*384  + (uint32_t)(lane&7)*48  + (uint32_t)((lane>>3)&1)*16;
  const uint32_t offB144 = (uint32_t)(lane>>4)*1152 + (uint32_t)(lane&7)*144 + (uint32_t)((lane>>3)&1)*16;

  // ---- stage weights (single fp16), once per persistent block ----
  for (int idx = t; idx < 16*64; idx += MLP_THREADS){
    int k = idx >> 6, n = idx & 63;
    *(__half*)(sm + SM_W0 + n*48 + k*2) = __float2half_rn(W0[idx]);
  }
  for (int idx = t; idx < 64*64; idx += MLP_THREADS){
    int k = idx >> 6, n = idx & 63;
    *(__half*)(sm + SM_W1 + n*144 + k*2) = __float2half_rn(W1[idx]);
  }
  for (int idx = t; idx < 64*288; idx += MLP_THREADS){
    int k = idx / 288, n = idx % 288;
    *(__half*)(sm + SM_W2 + n*144 + k*2) = __float2half_rn(W2[idx]);
  }

  int ntiles = (E + 255) >> 8;
  for (int tile = blockIdx.x; tile < ntiles; tile += gridDim.x){
    __syncthreads();   // previous iteration's X readers done
    // ---- stage x (256 edges x 16) as fp16 hi + scaled residual ----
    if (t < 256){
      int e = tile*256 + t;
      int ec = (e < E) ? e : (E - 1);
      const float4* src = (const float4*)(ef + (size_t)ec * NRBF);
      float4 v0 = src[0], v1 = src[1], v2 = src[2], v3 = src[3];
      float x[16] = { v0.x,v0.y,v0.z,v0.w, v1.x,v1.y,v1.z,v1.w,
                      v2.x,v2.y,v2.z,v2.w, v3.x,v3.y,v3.z,v3.w };
      uint32_t* xh = (uint32_t*)(sm + SM_XH + t*48);
      uint32_t* xl = (uint32_t*)(sm + SM_XL + t*48);
      #pragma unroll
      for (int c = 0; c < 8; ++c){
        uint32_t hi, lo;
        split2h(x[2*c], x[2*c+1], hi, lo);
        xh[c] = hi; xl[c] = lo;
      }
    }
    __syncthreads();

    // ---- A1 fragments from X (16 rows) via ldmatrix ----
    uint32_t a1h[4], a1l[4];
    ldm4(sm32 + SM_XH + (uint32_t)m0*48 + offA48, a1h);
    ldm4(sm32 + SM_XL + (uint32_t)m0*48 + offA48, a1l);

    // ---- Layer 1: 16 -> 64 ----
    uint32_t a2h[4][4], a2l[4][4];
    #pragma unroll
    for (int g = 0; g < 2; ++g){
      float accA[4][4], accB[4][4];
      #pragma unroll
      for (int j=0;j<4;++j)
        #pragma unroll
        for (int q=0;q<4;++q){ accA[j][q]=0.f; accB[j][q]=0.f; }
      uint32_t b01[4], b23[4];
      ldm4(sm32 + SM_W0 + (uint32_t)((g*4+0)*8)*48 + offB48, b01);
      ldm4(sm32 + SM_W0 + (uint32_t)((g*4+2)*8)*48 + offB48, b23);
      mma16816(accA[0], a1h, b01+0); mma16816(accA[1], a1h, b01+2);
      mma16816(accA[2], a1h, b23+0); mma16816(accA[3], a1h, b23+2);
      mma16816(accB[0], a1l, b01+0); mma16816(accB[1], a1l, b01+2);
      mma16816(accB[2], a1l, b23+0); mma16816(accB[3], a1l, b23+2);
      #pragma unroll
      for (int j=0;j<4;++j){
        int nt = g*4 + j, ks = nt >> 1, ix = (nt & 1) * 2;
        float y0 = silu_t(fmaf(accB[j][0], INV2048, accA[j][0]));
        float y1 = silu_t(fmaf(accB[j][1], INV2048, accA[j][1]));
        float y2 = silu_t(fmaf(accB[j][2], INV2048, accA[j][2]));
        float y3 = silu_t(fmaf(accB[j][3], INV2048, accA[j][3]));
        split2h(y0, y1, a2h[ks][ix],   a2l[ks][ix]);
        split2h(y2, y3, a2h[ks][ix+1], a2l[ks][ix+1]);
      }
    }

    // ---- Layer 2: 64 -> 64, K=64 (4 ksteps) ----
    uint32_t a3h[4][4], a3l[4][4];
    #pragma unroll
    for (int g = 0; g < 2; ++g){
      float accA[4][4], accB[4][4];
      #pragma unroll
      for (int j=0;j<4;++j)
        #pragma unroll
        for (int q=0;q<4;++q){ accA[j][q]=0.f; accB[j][q]=0.f; }
      #pragma unroll
      for (int ks = 0; ks < 4; ++ks){
        uint32_t b01[4], b23[4];
        ldm4(sm32 + SM_W1 + (uint32_t)((g*4+0)*8)*144 + (uint32_t)ks*32 + offB144, b01);
        ldm4(sm32 + SM_W1 + (uint32_t)((g*4+2)*8)*144 + (uint32_t)ks*32 + offB144, b23);
        mma16816(accA[0], a2h[ks], b01+0); mma16816(accA[1], a2h[ks], b01+2);
        mma16816(accA[2], a2h[ks], b23+0); mma16816(accA[3], a2h[ks], b23+2);
        mma16816(accB[0], a2l[ks], b01+0); mma16816(accB[1], a2l[ks], b01+2);
        mma16816(accB[2], a2l[ks], b23+0); mma16816(accB[3], a2l[ks], b23+2);
      }
      #pragma unroll
      for (int j=0;j<4;++j){
        int nt = g*4 + j, ks = nt >> 1, ix = (nt & 1) * 2;
        float y0 = silu_t(fmaf(accB[j][0], INV2048, accA[j][0]));
        float y1 = silu_t(fmaf(accB[j][1], INV2048, accA[j][1]));
        float y2 = silu_t(fmaf(accB[j][2], INV2048, accA[j][2]));
        float y3 = silu_t(fmaf(accB[j][3], INV2048, accA[j][3]));
        split2h(y0, y1, a3h[ks][ix],   a3l[ks][ix]);
        split2h(y2, y3, a3h[ks][ix+1], a3l[ks][ix+1]);
      }
    }

    // ---- Layer 3: 64 -> 288 (36 n-tiles, 9 groups of 4) ----
    #pragma unroll 1
    for (int g = 0; g < 9; ++g){
      float accA[4][4], accB[4][4];
      #pragma unroll
      for (int j=0;j<4;++j)
        #pragma unroll
        for (int q=0;q<4;++q){ accA[j][q]=0.f; accB[j][q]=0.f; }
      #pragma unroll
      for (int ks = 0; ks < 4; ++ks){
        uint32_t b01[4], b23[4];
        ldm4(sm32 + SM_W2 + (uint32_t)((g*4+0)*8)*144 + (uint32_t)ks*32 + offB144, b01);
        ldm4(sm32 + SM_W2 + (uint32_t)((g*4+2)*8)*144 + (uint32_t)ks*32 + offB144, b23);
        mma16816(accA[0], a3h[ks], b01+0); mma16816(accA[1], a3h[ks], b01+2);
        mma16816(accA[2], a3h[ks], b23+0); mma16816(accA[3], a3h[ks], b23+2);
        mma16816(accB[0], a3l[ks], b01+0); mma16816(accB[1], a3l[ks], b01+2);
        mma16816(accB[2], a3l[ks], b23+0); mma16816(accB[3], a3l[ks], b23+2);
      }
      // epilogue: merge residual, silu, fp16 store to g_w
      int e0 = tile*256 + m0 + grp;
      #pragma unroll
      for (int j=0;j<4;++j){
        int col = (g*4+j)*8 + 2*qt;
        float y0 = silu_t(fmaf(accB[j][0], INV2048, accA[j][0]));
        float y1 = silu_t(fmaf(accB[j][1], INV2048, accA[j][1]));
        float y2 = silu_t(fmaf(accB[j][2], INV2048, accA[j][2]));
        float y3 = silu_t(fmaf(accB[j][3], INV2048, accA[j][3]));
        if (e0 < E)
          *(__half2*)(&g_w[(size_t)e0*NW + col]) = __floats2half2_rn(y0, y1);
        if (e0 + 8 < E)
          *(__half2*)(&g_w[(size_t)(e0+8)*NW + col]) = __floats2half2_rn(y2, y3);
      }
    }
  }
}

// ============================================================
// Kernel B: tensor product + smem-staged coalesced scatter-add.
// ============================================================
template<int L1, int L2, int L3>
__device__ __forceinline__ void do_path(float wp, const float* x, const float* Y, float* o){
  constexpr CG3 cg = make_cg(L1, L2, L3);
  #pragma unroll
  for (int a = 0; a < 2*L1+1; ++a){
    float wx = wp * x[a];
    #pragma unroll
    for (int b = 0; b < 2*L2+1; ++b){
      #pragma unroll
      for (int c = 0; c < 2*L3+1; ++c){
        const float v = (float)cg.v[a][b][c];
        if (v != 0.0f){
          o[c] += wx * (v * Y[b]);
        }
      }
    }
  }
}

__global__ __launch_bounds__(256)
void tp_kernel(const float* __restrict__ nf,
               const float* __restrict__ evec,
               const int*   __restrict__ eidx,
               float* __restrict__ out,
               int E){
  __shared__ float sb[8][NW];
  int warp = (blockIdx.x * blockDim.x + threadIdx.x) >> 5;
  int wi = (threadIdx.x >> 5);
  int lane = threadIdx.x & 31;
  if (warp >= E) return;
  int e = warp;

  int src = eidx[2*e+0];
  int dst = eidx[2*e+1];

  float vx = evec[3*e+0], vy = evec[3*e+1], vz = evec[3*e+2];
  float nrm = sqrtf(vx*vx + vy*vy + vz*vz);
  float inv = 1.0f / (nrm + 1e-12f);
  float X = vx*inv, Yv = vy*inv, Z = vz*inv;

  const float S3 = 1.7320508075688772f;
  float Y0[1] = {1.0f};
  float Y1[3] = {Yv, Z, X};
  float Y2[5] = {S3*X*Yv, S3*Yv*Z, 0.5f*(3.0f*Z*Z - 1.0f), S3*X*Z, 0.5f*S3*(X*X - Yv*Yv)};

  const float* nfr = nf + (size_t)src * (4*CMUL);
  float x0[1] = { nfr[lane] };
  float x1[3] = { nfr[CMUL + 3*lane + 0],
                  nfr[CMUL + 3*lane + 1],
                  nfr[CMUL + 3*lane + 2] };

  const __half* wr = g_w + (size_t)e * NW;
  float o0[1] = {0.f};
  float o1[3] = {0.f,0.f,0.f};
  float o2[5] = {0.f,0.f,0.f,0.f,0.f};

  float wp0 = __half2float(wr[0*CMUL + lane]);
  float wp1 = __half2float(wr[1*CMUL + lane]);
  float wp2 = __half2float(wr[2*CMUL + lane]);
  float wp3 = __half2float(wr[3*CMUL + lane]);
  float wp4 = __half2float(wr[4*CMUL + lane]);
  float wp5 = __half2float(wr[5*CMUL + lane]);
  float wp6 = __half2float(wr[6*CMUL + lane]);
  float wp7 = __half2float(wr[7*CMUL + lane]);
  float wp8 = __half2float(wr[8*CMUL + lane]);

  do_path<0,0,0>(wp0, x0, Y0, o0);
  do_path<0,1,1>(wp1, x0, Y1, o1);
  do_path<0,2,2>(wp2, x0, Y2, o2);
  do_path<1,0,1>(wp3, x1, Y0, o1);
  do_path<1,1,0>(wp4, x1, Y1, o0);
  do_path<1,1,1>(wp5, x1, Y1, o1);
  do_path<1,1,2>(wp6, x1, Y1, o2);
  do_path<1,2,1>(wp7, x1, Y2, o1);
  do_path<1,2,2>(wp8, x1, Y2, o2);

  sb[wi][lane] = o0[0];
  #pragma unroll
  for (int c = 0; c < 3; ++c) sb[wi][CMUL + 3*lane + c] = o1[c];
  #pragma unroll
  for (int c = 0; c < 5; ++c) sb[wi][4*CMUL + 5*lane + c] = o2[c];
  __syncwarp();

  float* orow = out + (size_t)dst * NW;
  #pragma unroll
  for (int p = 0; p < 9; ++p)
    atomicAdd(orow + p*32 + lane, sb[wi][p*32 + lane]);
}

// ============================================================
// Launch
// ============================================================
extern "C" void kernel_launch(void* const* d_in, const int* in_sizes, int n_in,
                              void* d_out, int out_size){
  const float* nf = (const float*)d_in[0];
  const float* ef = (const float*)d_in[1];
  const float* ev = (const float*)d_in[2];
  const int*   ei = (const int*)  d_in[3];
  const float* W0 = (const float*)d_in[4];
  const float* W1 = (const float*)d_in[5];
  const float* W2 = (const float*)d_in[6];
  float* out = (float*)d_out;

  int E = in_sizes[2] / 3;
  if (E > MAX_E) E = MAX_E;

  cudaMemsetAsync(d_out, 0, (size_t)out_size * sizeof(float), 0);

  cudaFuncSetAttribute(mlp_mma_kernel, cudaFuncAttributeMaxDynamicSharedMemorySize, SM_TOT);
  mlp_mma_kernel<<<148, MLP_THREADS, SM_TOT>>>(ef, W0, W1, W2, E);

  int blocksB = (E * 32 + 255) / 256;
  tp_kernel<<<blocksB, 256>>>(nf, ev, ei, out, E);
}

// round 10
// speedup vs baseline: 4.4591x; 1.2064x over previous
#include <cuda_runtime.h>
#include <cuda_fp16.h>
#include <cstdint>
#include <cstddef>

// ============================================================
// Problem constants
// ============================================================
#define MAX_E   320000
#define NRBF    16
#define DH      64
#define NW      288
#define CMUL    32

// ============================================================
// Compile-time Clebsch-Gordan (exact port of the reference math)
// ============================================================
struct CD { double re, im; };
__host__ __device__ constexpr CD cmulc(CD a, CD b){ return CD{a.re*b.re - a.im*b.im, a.re*b.im + a.im*b.re}; }
__host__ __device__ constexpr CD conjc(CD a){ return CD{a.re, -a.im}; }
__host__ __device__ constexpr double cfact(int n){ double r=1.0; for(int i=2;i<=n;++i) r*= (double)i; return r; }
__host__ __device__ constexpr double csqrt(double x){
  if (x <= 0.0) return 0.0;
  double r = x < 1.0 ? 1.0 : x;
  for (int i=0;i<200;++i) r = 0.5*(r + x/r);
  return r;
}
__host__ __device__ constexpr double cgc(int l1,int l2,int l3,int m1,int m2){
  int m3 = m1+m2;
  if (m3 < -l3 || m3 > l3) return 0.0;
  double pref = csqrt((double)(2*l3+1)*cfact(l1+l2-l3)*cfact(l1-l2+l3)*cfact(-l1+l2+l3)/cfact(l1+l2+l3+1));
  pref *= csqrt(cfact(l3+m3)*cfact(l3-m3)*cfact(l1-m1)*cfact(l1+m1)*cfact(l2-m2)*cfact(l2+m2));
  double s = 0.0;
  for (int k=0;k<=l1+l2-l3;++k){
    int a1=l1+l2-l3-k, a2=l1-m1-k, a3=l2+m2-k, a4=l3-l2+m1+k, a5=l3-l1-m2+k;
    if (a1<0||a2<0||a3<0||a4<0||a5<0) continue;
    double d = cfact(k)*cfact(a1)*cfact(a2)*cfact(a3)*cfact(a4)*cfact(a5);
    s += ((k&1)? -1.0 : 1.0)/d;
  }
  return pref*s;
}
struct UMat { CD u[5][5]; };
__host__ __device__ constexpr UMat makeU(int l){
  UMat U{};
  const double s = 1.0/csqrt(2.0);
  U.u[l][l] = CD{1.0, 0.0};
  for (int m=1;m<=l;++m){
    double sg = (m&1)? -1.0 : 1.0;
    U.u[l+m][l+m] = CD{sg*s, 0.0};
    U.u[l+m][l-m] = CD{s, 0.0};
    U.u[l-m][l-m] = CD{0.0, s};
    U.u[l-m][l+m] = CD{0.0, -sg*s};
  }
  return U;
}
struct CG3 { double v[5][5][5]; };
__host__ __device__ constexpr CG3 make_cg(int l1,int l2,int l3){
  UMat U1 = makeU(l1), U2 = makeU(l2), U3 = makeU(l3);
  int n1=2*l1+1, n2=2*l2+1, n3=2*l3+1;
  double tre[5][5][5] = {}, tim[5][5][5] = {};
  double mre=0.0, mim=0.0;
  for (int a=0;a<n1;++a) for (int b=0;b<n2;++b) for (int c=0;c<n3;++c){
    CD acc{0.0,0.0};
    for (int m=0;m<n1;++m) for (int n=0;n<n2;++n){
      int o = (m-l1)+(n-l2)+l3;
      if (o < 0 || o >= n3) continue;
      double cg = cgc(l1,l2,l3, m-l1, n-l2);
      if (cg == 0.0) continue;
      CD t = cmulc(cmulc(U1.u[a][m], U2.u[b][n]), conjc(U3.u[c][o]));
      acc.re += t.re*cg; acc.im += t.im*cg;
    }
    tre[a][b][c]=acc.re; tim[a][b][c]=acc.im;
    double ar = acc.re<0.0?-acc.re:acc.re;
    double ai = acc.im<0.0?-acc.im:acc.im;
    if (ar>mre) mre=ar;
    if (ai>mim) mim=ai;
  }
  CG3 R{};
  for (int a=0;a<n1;++a) for (int b=0;b<n2;++b) for (int c=0;c<n3;++c){
    double vv = (mre >= mim) ? tre[a][b][c] : tim[a][b][c];
    if (vv < 1e-12 && vv > -1e-12) vv = 0.0;
    R.v[a][b][c] = vv;
  }
  return R;
}

// tanh-based silu: silu(x) = h + h*tanh(h), h = x/2.
__device__ __forceinline__ float silu_t(float x){
  float h = 0.5f * x;
  float t;
  asm("tanh.approx.f32 %0, %1;" : "=f"(t) : "f"(h));
  return fmaf(h, t, h);
}

#define INV2048 4.8828125e-4f

// ============================================================
// mma.sync m16n8k16 fp16
// ============================================================
__device__ __forceinline__ void mma16816(float d[4], const uint32_t a[4], const uint32_t b[2]){
  asm volatile("mma.sync.aligned.m16n8k16.row.col.f32.f16.f16.f32 "
    "{%0,%1,%2,%3}, {%4,%5,%6,%7}, {%8,%9}, {%0,%1,%2,%3};"
    : "+f"(d[0]), "+f"(d[1]), "+f"(d[2]), "+f"(d[3])
    : "r"(a[0]), "r"(a[1]), "r"(a[2]), "r"(a[3]), "r"(b[0]), "r"(b[1]));
}

__device__ __forceinline__ void ldm4(uint32_t addr, uint32_t* r){
  asm volatile("ldmatrix.sync.aligned.m8n8.x4.shared.b16 {%0,%1,%2,%3}, [%4];"
    : "=r"(r[0]), "=r"(r[1]), "=r"(r[2]), "=r"(r[3]) : "r"(addr));
}

// split into fp16 hi + fp16 residual scaled by 2048
__device__ __forceinline__ void split2h(float y0, float y1, uint32_t& hi, uint32_t& lo){
  uint32_t h;
  asm("cvt.rn.f16x2.f32 %0, %1, %2;" : "=r"(h) : "f"(y1), "f"(y0));
  __half2 hh = *reinterpret_cast<__half2*>(&h);
  float2 hf = __half22float2(hh);
  float r0 = (y0 - hf.x) * 2048.0f;
  float r1 = (y1 - hf.y) * 2048.0f;
  uint32_t l;
  asm("cvt.rn.f16x2.f32 %0, %1, %2;" : "=r"(l) : "f"(r1), "f"(r0));
  hi = h; lo = l;
}
__device__ __forceinline__ uint32_t pack_h2(float y0, float y1){
  uint32_t h;
  asm("cvt.rn.f16x2.f32 %0, %1, %2;" : "=r"(h) : "f"(y1), "f"(y0));
  return h;
}

// ============================================================
// SMEM layout (bytes).
//  Weights fp16 [n][k], padded rows (48B for K=16, 144B for K=64).
//  XH/XL (input staging) OVERLAYS the wbuf region (disjoint lifetimes).
//  wbuf: per-warp 16 edges x 288 halves, row stride 592B (bank-perfect).
//  sb:   per-warp 288-float message staging for coalesced atomics.
// ============================================================
#define SM_W0   0          // 64 * 48   = 3072
#define SM_W1   3072       // 64 * 144  = 9216
#define SM_W2   12288      // 288 * 144 = 41472
#define SM_DYN  53760
#define SM_XH   SM_DYN             // 256*48 = 12288
#define SM_XL   (SM_DYN + 12288)   // 256*48 = 12288
#define WB_ROW  592
#define WB_WARP (16*WB_ROW)        // 9472
#define SM_WBUF SM_DYN             // 16 warps * 9472 = 151552
#define SM_SB   (SM_DYN + 16*WB_WARP)   // 205312
#define SM_TOT  (SM_SB + 16*NW*4)       // 223744

#define FT_THREADS 512   // 16 warps x 16 edges = 256-edge tiles

template<int L1, int L2, int L3>
__device__ __forceinline__ void do_path(float wp, const float* x, const float* Y, float* o){
  constexpr CG3 cg = make_cg(L1, L2, L3);
  #pragma unroll
  for (int a = 0; a < 2*L1+1; ++a){
    float wx = wp * x[a];
    #pragma unroll
    for (int b = 0; b < 2*L2+1; ++b){
      #pragma unroll
      for (int c = 0; c < 2*L3+1; ++c){
        const float v = (float)cg.v[a][b][c];
        if (v != 0.0f) o[c] += wx * (v * Y[b]);
      }
    }
  }
}

__global__ __launch_bounds__(FT_THREADS)
void fused_kernel(const float* __restrict__ nf,
                  const float* __restrict__ ef,
                  const float* __restrict__ evec,
                  const int*   __restrict__ eidx,
                  const float* __restrict__ W0,
                  const float* __restrict__ W1,
                  const float* __restrict__ W2,
                  float* __restrict__ out,
                  int E){
  extern __shared__ char sm[];
  uint32_t sm32 = (uint32_t)__cvta_generic_to_shared(sm);
  int t = threadIdx.x;
  int lane = t & 31, wid = t >> 5;
  int grp = lane >> 2, qt = lane & 3;
  int m0 = wid * 16;

  const uint32_t offA48  = ((uint32_t)(((lane>>3)&1)*8 + (lane&7)))*48 + (uint32_t)(lane>>4)*16;
  const uint32_t offB48  = (uint32_t)(lane>>4)*384  + (uint32_t)(lane&7)*48  + (uint32_t)((lane>>3)&1)*16;
  const uint32_t offB144 = (uint32_t)(lane>>4)*1152 + (uint32_t)(lane&7)*144 + (uint32_t)((lane>>3)&1)*16;

  // ---- stage weights (fp16), once per persistent block ----
  for (int idx = t; idx < 16*64; idx += FT_THREADS){
    int k = idx >> 6, n = idx & 63;
    *(__half*)(sm + SM_W0 + n*48 + k*2) = __float2half_rn(W0[idx]);
  }
  for (int idx = t; idx < 64*64; idx += FT_THREADS){
    int k = idx >> 6, n = idx & 63;
    *(__half*)(sm + SM_W1 + n*144 + k*2) = __float2half_rn(W1[idx]);
  }
  for (int idx = t; idx < 64*288; idx += FT_THREADS){
    int k = idx / 288, n = idx % 288;
    *(__half*)(sm + SM_W2 + n*144 + k*2) = __float2half_rn(W2[idx]);
  }

  char* wb = sm + SM_WBUF + wid * WB_WARP;
  float* sbw = (float*)(sm + SM_SB + wid * NW * 4);

  int ntiles = (E + 255) >> 8;
  for (int tile = blockIdx.x; tile < ntiles; tile += gridDim.x){
    __syncthreads();   // (A) prior-iter wbuf reads done before X overlay writes
    // ---- stage x (256 edges x 16) as fp16 hi + scaled residual ----
    if (t < 256){
      int e = tile*256 + t;
      int ec = (e < E) ? e : (E - 1);
      const float4* src = (const float4*)(ef + (size_t)ec * NRBF);
      float4 v0 = src[0], v1 = src[1], v2 = src[2], v3 = src[3];
      float x[16] = { v0.x,v0.y,v0.z,v0.w, v1.x,v1.y,v1.z,v1.w,
                      v2.x,v2.y,v2.z,v2.w, v3.x,v3.y,v3.z,v3.w };
      uint32_t* xh = (uint32_t*)(sm + SM_XH + t*48);
      uint32_t* xl = (uint32_t*)(sm + SM_XL + t*48);
      #pragma unroll
      for (int c = 0; c < 8; ++c){
        uint32_t hi, lo;
        split2h(x[2*c], x[2*c+1], hi, lo);
        xh[c] = hi; xl[c] = lo;
      }
    }
    __syncthreads();   // (B) X ready

    uint32_t a1h[4], a1l[4];
    ldm4(sm32 + SM_XH + (uint32_t)m0*48 + offA48, a1h);
    ldm4(sm32 + SM_XL + (uint32_t)m0*48 + offA48, a1l);
    __syncthreads();   // (C) all warps done reading X before wbuf writes

    // ---- Layer 1: 16 -> 64, A split-2 ----
    uint32_t a2h[4][4], a2l[4][4];
    #pragma unroll
    for (int g = 0; g < 2; ++g){
      float accA[4][4], accB[4][4];
      #pragma unroll
      for (int j=0;j<4;++j)
        #pragma unroll
        for (int q=0;q<4;++q){ accA[j][q]=0.f; accB[j][q]=0.f; }
      uint32_t b01[4], b23[4];
      ldm4(sm32 + SM_W0 + (uint32_t)((g*4+0)*8)*48 + offB48, b01);
      ldm4(sm32 + SM_W0 + (uint32_t)((g*4+2)*8)*48 + offB48, b23);
      mma16816(accA[0], a1h, b01+0); mma16816(accA[1], a1h, b01+2);
      mma16816(accA[2], a1h, b23+0); mma16816(accA[3], a1h, b23+2);
      mma16816(accB[0], a1l, b01+0); mma16816(accB[1], a1l, b01+2);
      mma16816(accB[2], a1l, b23+0); mma16816(accB[3], a1l, b23+2);
      #pragma unroll
      for (int j=0;j<4;++j){
        int nt = g*4 + j, ks = nt >> 1, ix = (nt & 1) * 2;
        float y0 = silu_t(fmaf(accB[j][0], INV2048, accA[j][0]));
        float y1 = silu_t(fmaf(accB[j][1], INV2048, accA[j][1]));
        float y2 = silu_t(fmaf(accB[j][2], INV2048, accA[j][2]));
        float y3 = silu_t(fmaf(accB[j][3], INV2048, accA[j][3]));
        split2h(y0, y1, a2h[ks][ix],   a2l[ks][ix]);
        split2h(y2, y3, a2h[ks][ix+1], a2l[ks][ix+1]);
      }
    }

    // ---- Layer 2: 64 -> 64, A split-2; output hi-only fragments ----
    uint32_t a3h[4][4];
    #pragma unroll
    for (int g = 0; g < 2; ++g){
      float accA[4][4], accB[4][4];
      #pragma unroll
      for (int j=0;j<4;++j)
        #pragma unroll
        for (int q=0;q<4;++q){ accA[j][q]=0.f; accB[j][q]=0.f; }
      #pragma unroll
      for (int ks = 0; ks < 4; ++ks){
        uint32_t b01[4], b23[4];
        ldm4(sm32 + SM_W1 + (uint32_t)((g*4+0)*8)*144 + (uint32_t)ks*32 + offB144, b01);
        ldm4(sm32 + SM_W1 + (uint32_t)((g*4+2)*8)*144 + (uint32_t)ks*32 + offB144, b23);
        mma16816(accA[0], a2h[ks], b01+0); mma16816(accA[1], a2h[ks], b01+2);
        mma16816(accA[2], a2h[ks], b23+0); mma16816(accA[3], a2h[ks], b23+2);
        mma16816(accB[0], a2l[ks], b01+0); mma16816(accB[1], a2l[ks], b01+2);
        mma16816(accB[2], a2l[ks], b23+0); mma16816(accB[3], a2l[ks], b23+2);
      }
      #pragma unroll
      for (int j=0;j<4;++j){
        int nt = g*4 + j, ks = nt >> 1, ix = (nt & 1) * 2;
        float y0 = silu_t(fmaf(accB[j][0], INV2048, accA[j][0]));
        float y1 = silu_t(fmaf(accB[j][1], INV2048, accA[j][1]));
        float y2 = silu_t(fmaf(accB[j][2], INV2048, accA[j][2]));
        float y3 = silu_t(fmaf(accB[j][3], INV2048, accA[j][3]));
        a3h[ks][ix]   = pack_h2(y0, y1);
        a3h[ks][ix+1] = pack_h2(y2, y3);
      }
    }

    // ---- Layer 3: 64 -> 288, A hi-only; write into per-warp wbuf ----
    #pragma unroll 1
    for (int g = 0; g < 9; ++g){
      float accA[4][4];
      #pragma unroll
      for (int j=0;j<4;++j)
        #pragma unroll
        for (int q=0;q<4;++q) accA[j][q]=0.f;
      #pragma unroll
      for (int ks = 0; ks < 4; ++ks){
        uint32_t b01[4], b23[4];
        ldm4(sm32 + SM_W2 + (uint32_t)((g*4+0)*8)*144 + (uint32_t)ks*32 + offB144, b01);
        ldm4(sm32 + SM_W2 + (uint32_t)((g*4+2)*8)*144 + (uint32_t)ks*32 + offB144, b23);
        mma16816(accA[0], a3h[ks], b01+0); mma16816(accA[1], a3h[ks], b01+2);
        mma16816(accA[2], a3h[ks], b23+0); mma16816(accA[3], a3h[ks], b23+2);
      }
      #pragma unroll
      for (int j=0;j<4;++j){
        int col = (g*4+j)*8 + 2*qt;
        float y0 = silu_t(accA[j][0]);
        float y1 = silu_t(accA[j][1]);
        float y2 = silu_t(accA[j][2]);
        float y3 = silu_t(accA[j][3]);
        *(uint32_t*)(wb + grp*WB_ROW + col*2)     = pack_h2(y0, y1);
        *(uint32_t*)(wb + (grp+8)*WB_ROW + col*2) = pack_h2(y2, y3);
      }
    }
    __syncwarp();

    // ---- TP phase: 16 edges sequential, lane = channel ----
    int base_e = tile*256 + m0;
    // prefetch el=0
    int psrc=0, pdst=0; float pvx=0.f,pvy=0.f,pvz=0.f;
    float px0=0.f, px1a=0.f, px1b=0.f, px1c=0.f;
    if (base_e < E){
      psrc = eidx[2*base_e]; pdst = eidx[2*base_e+1];
      pvx = evec[3*base_e]; pvy = evec[3*base_e+1]; pvz = evec[3*base_e+2];
      const float* nfr = nf + (size_t)psrc * (4*CMUL);
      px0  = nfr[lane];
      px1a = nfr[CMUL + 3*lane + 0];
      px1b = nfr[CMUL + 3*lane + 1];
      px1c = nfr[CMUL + 3*lane + 2];
    }
    #pragma unroll 1
    for (int el = 0; el < 16; ++el){
      int e = base_e + el;
      if (e >= E) break;
      int dst = pdst;
      float vx = pvx, vy = pvy, vz = pvz;
      float x0v = px0, x1a = px1a, x1b = px1b, x1c = px1c;
      int ne = e + 1;
      if (el < 15 && ne < E){
        psrc = eidx[2*ne]; pdst = eidx[2*ne+1];
        pvx = evec[3*ne]; pvy = evec[3*ne+1]; pvz = evec[3*ne+2];
        const float* nfr = nf + (size_t)psrc * (4*CMUL);
        px0  = nfr[lane];
        px1a = nfr[CMUL + 3*lane + 0];
        px1b = nfr[CMUL + 3*lane + 1];
        px1c = nfr[CMUL + 3*lane + 2];
      }

      float nrm = sqrtf(vx*vx + vy*vy + vz*vz);
      float inv = 1.0f / (nrm + 1e-12f);
      float X = vx*inv, Yv = vy*inv, Z = vz*inv;
      const float S3 = 1.7320508075688772f;
      float Y0a[1] = {1.0f};
      float Y1a[3] = {Yv, Z, X};
      float Y2a[5] = {S3*X*Yv, S3*Yv*Z, 0.5f*(3.0f*Z*Z - 1.0f), S3*X*Z, 0.5f*S3*(X*X - Yv*Yv)};

      float x0[1] = { x0v };
      float x1[3] = { x1a, x1b, x1c };

      const __half* wr = (const __half*)(wb + el*WB_ROW);
      float o0[1] = {0.f};
      float o1[3] = {0.f,0.f,0.f};
      float o2[5] = {0.f,0.f,0.f,0.f,0.f};

      float wp0 = __half2float(wr[0*CMUL + lane]);
      float wp1 = __half2float(wr[1*CMUL + lane]);
      float wp2 = __half2float(wr[2*CMUL + lane]);
      float wp3 = __half2float(wr[3*CMUL + lane]);
      float wp4 = __half2float(wr[4*CMUL + lane]);
      float wp5 = __half2float(wr[5*CMUL + lane]);
      float wp6 = __half2float(wr[6*CMUL + lane]);
      float wp7 = __half2float(wr[7*CMUL + lane]);
      float wp8 = __half2float(wr[8*CMUL + lane]);

      do_path<0,0,0>(wp0, x0, Y0a, o0);
      do_path<0,1,1>(wp1, x0, Y1a, o1);
      do_path<0,2,2>(wp2, x0, Y2a, o2);
      do_path<1,0,1>(wp3, x1, Y0a, o1);
      do_path<1,1,0>(wp4, x1, Y1a, o0);
      do_path<1,1,1>(wp5, x1, Y1a, o1);
      do_path<1,1,2>(wp6, x1, Y1a, o2);
      do_path<1,2,1>(wp7, x1, Y2a, o1);
      do_path<1,2,2>(wp8, x1, Y2a, o2);

      // stage message (strides 1/3/5: conflict-free)
      sbw[lane] = o0[0];
      #pragma unroll
      for (int c = 0; c < 3; ++c) sbw[CMUL + 3*lane + c] = o1[c];
      #pragma unroll
      for (int c = 0; c < 5; ++c) sbw[4*CMUL + 5*lane + c] = o2[c];
      __syncwarp();

      float* orow = out + (size_t)dst * NW;
      #pragma unroll
      for (int p = 0; p < 9; ++p)
        atomicAdd(orow + p*32 + lane, sbw[p*32 + lane]);
      __syncwarp();
    }
  }
}

// ============================================================
// Launch
// ============================================================
extern "C" void kernel_launch(void* const* d_in, const int* in_sizes, int n_in,
                              void* d_out, int out_size){
  const float* nf = (const float*)d_in[0];
  const float* ef = (const float*)d_in[1];
  const float* ev = (const float*)d_in[2];
  const int*   ei = (const int*)  d_in[3];
  const float* W0 = (const float*)d_in[4];
  const float* W1 = (const float*)d_in[5];
  const float* W2 = (const float*)d_in[6];
  float* out = (float*)d_out;

  int E = in_sizes[2] / 3;
  if (E > MAX_E) E = MAX_E;

  cudaMemsetAsync(d_out, 0, (size_t)out_size * sizeof(float), 0);

  cudaFuncSetAttribute(fused_kernel, cudaFuncAttributeMaxDynamicSharedMemorySize, SM_TOT);
  fused_kernel<<<148, FT_THREADS, SM_TOT>>>(nf, ef, ev, ei, W0, W1, W2, out, E);
}